// round 11
// baseline (speedup 1.0000x reference)
#include <cuda_runtime.h>
#include <cuda_bf16.h>
#include <cuda_fp16.h>
#include <math.h>

#define N_NODES 100000
#define E_EDGES 3200000
#define NFEAT 256
#define NHID 128
#define NCLASS 64

#define SCAN_CHUNK 1024
#define SCAN_NB ((N_NODES + SCAN_CHUNK - 1) / SCAN_CHUNK)   // 98

// Scratch (allocation-free rule: __device__ globals)
__device__ __align__(256) __half g_tmph[(size_t)N_NODES * NHID];   // GEMM out (fp16)
__device__ __align__(256) __half g_hh[(size_t)N_NODES * NHID];     // SpMM out (fp16)
__device__ __align__(256) float g_nsrc[N_NODES];
__device__ __align__(256) float g_ndst[N_NODES];
__device__ __align__(256) int g_degout[N_NODES];
__device__ __align__(256) int g_degin[N_NODES];
__device__ __align__(256) int g_rowptr[N_NODES + 1];
__device__ __align__(256) int g_cursor[N_NODES];
__device__ __align__(256) int g_csr[E_EDGES];
__device__ __align__(256) int g_blocksums[SCAN_NB];

// f32x2 helpers
__device__ __forceinline__ unsigned long long pack2(float lo, float hi) {
    unsigned long long r;
    asm("mov.b64 %0, {%1, %2};" : "=l"(r) : "f"(lo), "f"(hi));
    return r;
}
__device__ __forceinline__ void fma2(unsigned long long& acc,
                                     unsigned long long a,
                                     unsigned long long b) {
    asm("fma.rn.f32x2 %0, %1, %2, %0;" : "+l"(acc) : "l"(a), "l"(b));
}
__device__ __forceinline__ float2 unpack2(unsigned long long v) {
    float lo, hi;
    asm("mov.b64 {%0, %1}, %2;" : "=f"(lo), "=f"(hi) : "l"(v));
    return make_float2(lo, hi);
}
__device__ __forceinline__ float2 h2f(unsigned u) {
    return __half22float2(*reinterpret_cast<__half2*>(&u));
}

// ---------------- degree / norms ----------------

__global__ void zero_deg_k() {
    int i = blockIdx.x * blockDim.x + threadIdx.x;
    if (i < N_NODES) { g_degout[i] = 0; g_degin[i] = 0; }
}

__global__ void degree_k(const int* __restrict__ src,
                         const int* __restrict__ dst) {
    int e = blockIdx.x * blockDim.x + threadIdx.x;
    if (e < E_EDGES) {
        atomicAdd(&g_degout[src[e]], 1);
        atomicAdd(&g_degin[dst[e]], 1);
    }
}

__global__ void norms_k() {
    int i = blockIdx.x * blockDim.x + threadIdx.x;
    if (i < N_NODES) {
        int dov = g_degout[i];
        int div_ = g_degin[i];
        g_nsrc[i] = rsqrtf((float)(dov > 0 ? dov : 1));
        g_ndst[i] = rsqrtf((float)(div_ > 0 ? div_ : 1));
    }
}

// ---------------- 3-phase exclusive scan of deg_in -> rowptr/cursor ----------------

__global__ void blocksum_k() {
    int base = blockIdx.x * SCAN_CHUNK;
    int tid = threadIdx.x;
    int s = 0;
#pragma unroll
    for (int j = 0; j < 4; j++) {
        int idx = base + tid * 4 + j;
        if (idx < N_NODES) s += g_degin[idx];
    }
#pragma unroll
    for (int o = 16; o > 0; o >>= 1) s += __shfl_xor_sync(0xffffffffu, s, o);
    __shared__ int ws[8];
    if ((tid & 31) == 0) ws[tid >> 5] = s;
    __syncthreads();
    if (tid == 0) {
        int t = 0;
#pragma unroll
        for (int w = 0; w < 8; w++) t += ws[w];
        g_blocksums[blockIdx.x] = t;
    }
}

__global__ void scanblocks_k() {
    __shared__ int s[128];
    int tid = threadIdx.x;
    int v = (tid < SCAN_NB) ? g_blocksums[tid] : 0;
    s[tid] = v;
    __syncthreads();
#pragma unroll
    for (int off = 1; off < 128; off <<= 1) {
        int t = (tid >= off) ? s[tid - off] : 0;
        __syncthreads();
        s[tid] += t;
        __syncthreads();
    }
    if (tid < SCAN_NB) g_blocksums[tid] = s[tid] - v;  // exclusive
}

__global__ void localscan_k() {
    int base = blockIdx.x * SCAN_CHUNK;
    int tid = threadIdx.x;
    int lane = tid & 31;
    int warp = tid >> 5;

    int e0 = base + tid * 4;
    int d0 = (e0 + 0 < N_NODES) ? g_degin[e0 + 0] : 0;
    int d1 = (e0 + 1 < N_NODES) ? g_degin[e0 + 1] : 0;
    int d2 = (e0 + 2 < N_NODES) ? g_degin[e0 + 2] : 0;
    int d3 = (e0 + 3 < N_NODES) ? g_degin[e0 + 3] : 0;
    int tsum = d0 + d1 + d2 + d3;

    int inc = tsum;
#pragma unroll
    for (int o = 1; o < 32; o <<= 1) {
        int t = __shfl_up_sync(0xffffffffu, inc, o);
        if (lane >= o) inc += t;
    }
    __shared__ int wsum[8];
    if (lane == 31) wsum[warp] = inc;
    __syncthreads();
    __shared__ int woff[8];
    if (tid == 0) {
        int acc = 0;
#pragma unroll
        for (int w = 0; w < 8; w++) { woff[w] = acc; acc += wsum[w]; }
    }
    __syncthreads();

    int thread_excl = g_blocksums[blockIdx.x] + woff[warp] + (inc - tsum);
    int p0 = thread_excl;
    int p1 = p0 + d0;
    int p2 = p1 + d1;
    int p3 = p2 + d2;
    if (e0 + 0 < N_NODES) { g_rowptr[e0 + 0] = p0; g_cursor[e0 + 0] = p0; }
    if (e0 + 1 < N_NODES) { g_rowptr[e0 + 1] = p1; g_cursor[e0 + 1] = p1; }
    if (e0 + 2 < N_NODES) { g_rowptr[e0 + 2] = p2; g_cursor[e0 + 2] = p2; }
    if (e0 + 3 < N_NODES) { g_rowptr[e0 + 3] = p3; g_cursor[e0 + 3] = p3; }
    if (blockIdx.x == 0 && tid == 0) g_rowptr[N_NODES] = E_EDGES;
}

__global__ void scatter_k(const int* __restrict__ src,
                          const int* __restrict__ dst) {
    int e = blockIdx.x * blockDim.x + threadIdx.x;
    if (e < E_EDGES) {
        int pos = atomicAdd(&g_cursor[dst[e]], 1);
        g_csr[pos] = src[e];
    }
}

// ---------------- GEMM: tmp16[i,j] = (sum_k H[i,k] W[k,j]) [* n_src[i] if SCALE] ------------
// fp32 accumulate (FFMA2), fp16 packed output. Input fp32 or fp16. 128 threads, 32-row tile.
template <int IN, int OUT, bool SCALE, typename T>
__global__ void gemm_h_k(const T* __restrict__ H,
                         const float* __restrict__ W,
                         __half* __restrict__ out) {
    constexpr int CG = OUT / 4;     // col groups (thread handles 4 cols = 2 pairs)
    constexpr int RG = 128 / CG;    // row groups
    constexpr int R = 32 / RG;      // rows per thread
    __shared__ float Hs[32 * IN];

    int tid = threadIdx.x;
    int row0 = blockIdx.x * 32;

    if constexpr (sizeof(T) == 4) {
        const float4* Hg = reinterpret_cast<const float4*>((const float*)H + (size_t)row0 * IN);
        float4* Hs4 = reinterpret_cast<float4*>(Hs);
#pragma unroll
        for (int i = tid; i < 32 * IN / 4; i += 128) Hs4[i] = Hg[i];
    } else {
        const uint4* Hg = reinterpret_cast<const uint4*>((const __half*)H + (size_t)row0 * IN);
#pragma unroll
        for (int i = tid; i < 32 * IN / 8; i += 128) {
            uint4 u = Hg[i];
            float* d = Hs + (size_t)i * 8;
            float2 f0 = h2f(u.x), f1 = h2f(u.y), f2 = h2f(u.z), f3 = h2f(u.w);
            d[0] = f0.x; d[1] = f0.y; d[2] = f1.x; d[3] = f1.y;
            d[4] = f2.x; d[5] = f2.y; d[6] = f3.x; d[7] = f3.y;
        }
    }
    __syncthreads();

    int tx = tid % CG;
    int ty = tid / CG;
    const float* hbase = Hs + (size_t)(ty * R) * IN;

    unsigned long long acc[R][2];
#pragma unroll
    for (int r = 0; r < R; r++) { acc[r][0] = 0ull; acc[r][1] = 0ull; }

    for (int k = 0; k < IN; k += 2) {
        float4 w0 = *reinterpret_cast<const float4*>(W + (size_t)k * OUT + tx * 4);
        float4 w1 = *reinterpret_cast<const float4*>(W + (size_t)(k + 1) * OUT + tx * 4);
        unsigned long long w0a = pack2(w0.x, w0.y);
        unsigned long long w0b = pack2(w0.z, w0.w);
        unsigned long long w1a = pack2(w1.x, w1.y);
        unsigned long long w1b = pack2(w1.z, w1.w);
#pragma unroll
        for (int r = 0; r < R; r++) {
            float2 hv = *reinterpret_cast<const float2*>(hbase + (size_t)r * IN + k);
            unsigned long long hx = pack2(hv.x, hv.x);
            unsigned long long hy = pack2(hv.y, hv.y);
            fma2(acc[r][0], hx, w0a);
            fma2(acc[r][1], hx, w0b);
            fma2(acc[r][0], hy, w1a);
            fma2(acc[r][1], hy, w1b);
        }
    }

#pragma unroll
    for (int r = 0; r < R; r++) {
        int row = row0 + ty * R + r;
        float ns = SCALE ? g_nsrc[row] : 1.0f;
        float2 lo = unpack2(acc[r][0]);
        float2 hi = unpack2(acc[r][1]);
        __half2 p0 = __floats2half2_rn(lo.x * ns, lo.y * ns);
        __half2 p1 = __floats2half2_rn(hi.x * ns, hi.y * ns);
        uint2 st = make_uint2(*reinterpret_cast<unsigned*>(&p0),
                              *reinterpret_cast<unsigned*>(&p1));
        *reinterpret_cast<uint2*>(out + (size_t)row * OUT + tx * 4) = st;
    }
}

// ---------------- CSR SpMM (fp16), fused finalize. Subwarp-16 per dst node. ---------------
// 16 lanes per node, 8 halves (uint4) per lane for 128 features. fp32 accumulate, fp16 out.
template <bool SRCSCALE>
__global__ void spmm_csr128h_k(const __half* __restrict__ tmp,
                               const float* __restrict__ b,
                               __half* __restrict__ h) {
    int gtid = blockIdx.x * blockDim.x + threadIdx.x;
    int w = gtid >> 4;
    int sl = threadIdx.x & 15;
    if (w >= N_NODES) return;
    int beg = g_rowptr[w];
    int end = g_rowptr[w + 1];
    float acc[8] = {0.f, 0.f, 0.f, 0.f, 0.f, 0.f, 0.f, 0.f};
    int i = beg;
    for (; i + 3 < end; i += 4) {
        int s0 = g_csr[i], s1 = g_csr[i + 1], s2 = g_csr[i + 2], s3 = g_csr[i + 3];
        uint4 u0 = *reinterpret_cast<const uint4*>(tmp + (size_t)s0 * 128 + sl * 8);
        uint4 u1 = *reinterpret_cast<const uint4*>(tmp + (size_t)s1 * 128 + sl * 8);
        uint4 u2 = *reinterpret_cast<const uint4*>(tmp + (size_t)s2 * 128 + sl * 8);
        uint4 u3 = *reinterpret_cast<const uint4*>(tmp + (size_t)s3 * 128 + sl * 8);
        float n0 = 1.f, n1 = 1.f, n2 = 1.f, n3 = 1.f;
        if (SRCSCALE) {
            n0 = __ldg(&g_nsrc[s0]); n1 = __ldg(&g_nsrc[s1]);
            n2 = __ldg(&g_nsrc[s2]); n3 = __ldg(&g_nsrc[s3]);
        }
        float2 f;
        f = h2f(u0.x); acc[0] += f.x * n0; acc[1] += f.y * n0;
        f = h2f(u0.y); acc[2] += f.x * n0; acc[3] += f.y * n0;
        f = h2f(u0.z); acc[4] += f.x * n0; acc[5] += f.y * n0;
        f = h2f(u0.w); acc[6] += f.x * n0; acc[7] += f.y * n0;
        f = h2f(u1.x); acc[0] += f.x * n1; acc[1] += f.y * n1;
        f = h2f(u1.y); acc[2] += f.x * n1; acc[3] += f.y * n1;
        f = h2f(u1.z); acc[4] += f.x * n1; acc[5] += f.y * n1;
        f = h2f(u1.w); acc[6] += f.x * n1; acc[7] += f.y * n1;
        f = h2f(u2.x); acc[0] += f.x * n2; acc[1] += f.y * n2;
        f = h2f(u2.y); acc[2] += f.x * n2; acc[3] += f.y * n2;
        f = h2f(u2.z); acc[4] += f.x * n2; acc[5] += f.y * n2;
        f = h2f(u2.w); acc[6] += f.x * n2; acc[7] += f.y * n2;
        f = h2f(u3.x); acc[0] += f.x * n3; acc[1] += f.y * n3;
        f = h2f(u3.y); acc[2] += f.x * n3; acc[3] += f.y * n3;
        f = h2f(u3.z); acc[4] += f.x * n3; acc[5] += f.y * n3;
        f = h2f(u3.w); acc[6] += f.x * n3; acc[7] += f.y * n3;
    }
    for (; i < end; i++) {
        int s = g_csr[i];
        uint4 u = *reinterpret_cast<const uint4*>(tmp + (size_t)s * 128 + sl * 8);
        float ns = SRCSCALE ? __ldg(&g_nsrc[s]) : 1.0f;
        float2 f;
        f = h2f(u.x); acc[0] += f.x * ns; acc[1] += f.y * ns;
        f = h2f(u.y); acc[2] += f.x * ns; acc[3] += f.y * ns;
        f = h2f(u.z); acc[4] += f.x * ns; acc[5] += f.y * ns;
        f = h2f(u.w); acc[6] += f.x * ns; acc[7] += f.y * ns;
    }
    float nd = g_ndst[w];
    float4 b0_ = *reinterpret_cast<const float4*>(b + sl * 8);
    float4 b1_ = *reinterpret_cast<const float4*>(b + sl * 8 + 4);
    __half2 p0 = __floats2half2_rn(acc[0] * nd + b0_.x, acc[1] * nd + b0_.y);
    __half2 p1 = __floats2half2_rn(acc[2] * nd + b0_.z, acc[3] * nd + b0_.w);
    __half2 p2 = __floats2half2_rn(acc[4] * nd + b1_.x, acc[5] * nd + b1_.y);
    __half2 p3 = __floats2half2_rn(acc[6] * nd + b1_.z, acc[7] * nd + b1_.w);
    uint4 st = make_uint4(*reinterpret_cast<unsigned*>(&p0),
                          *reinterpret_cast<unsigned*>(&p1),
                          *reinterpret_cast<unsigned*>(&p2),
                          *reinterpret_cast<unsigned*>(&p3));
    *reinterpret_cast<uint4*>(h + (size_t)w * 128 + sl * 8) = st;
}

// 64 features fp16 gather, fused finalize + softmax. Subwarp-16, 4 halves (uint2) per lane.
__global__ void spmm_csr64h_softmax_k(const __half* __restrict__ tmp,
                                      const float* __restrict__ b,
                                      float* __restrict__ out) {
    int gtid = blockIdx.x * blockDim.x + threadIdx.x;
    int w = gtid >> 4;
    int sl = threadIdx.x & 15;
    if (w >= N_NODES) return;
    int beg = g_rowptr[w];
    int end = g_rowptr[w + 1];
    float acc[4] = {0.f, 0.f, 0.f, 0.f};
    int i = beg;
    for (; i + 3 < end; i += 4) {
        int s0 = g_csr[i], s1 = g_csr[i + 1], s2 = g_csr[i + 2], s3 = g_csr[i + 3];
        uint2 u0 = *reinterpret_cast<const uint2*>(tmp + (size_t)s0 * 64 + sl * 4);
        uint2 u1 = *reinterpret_cast<const uint2*>(tmp + (size_t)s1 * 64 + sl * 4);
        uint2 u2 = *reinterpret_cast<const uint2*>(tmp + (size_t)s2 * 64 + sl * 4);
        uint2 u3 = *reinterpret_cast<const uint2*>(tmp + (size_t)s3 * 64 + sl * 4);
        float2 f;
        f = h2f(u0.x); acc[0] += f.x; acc[1] += f.y;
        f = h2f(u0.y); acc[2] += f.x; acc[3] += f.y;
        f = h2f(u1.x); acc[0] += f.x; acc[1] += f.y;
        f = h2f(u1.y); acc[2] += f.x; acc[3] += f.y;
        f = h2f(u2.x); acc[0] += f.x; acc[1] += f.y;
        f = h2f(u2.y); acc[2] += f.x; acc[3] += f.y;
        f = h2f(u3.x); acc[0] += f.x; acc[1] += f.y;
        f = h2f(u3.y); acc[2] += f.x; acc[3] += f.y;
    }
    for (; i < end; i++) {
        int s = g_csr[i];
        uint2 u = *reinterpret_cast<const uint2*>(tmp + (size_t)s * 64 + sl * 4);
        float2 f;
        f = h2f(u.x); acc[0] += f.x; acc[1] += f.y;
        f = h2f(u.y); acc[2] += f.x; acc[3] += f.y;
    }
    float nd = g_ndst[w];
    float4 bb = *reinterpret_cast<const float4*>(b + sl * 4);
    float a0 = acc[0] * nd + bb.x;
    float a1 = acc[1] * nd + bb.y;
    float a2 = acc[2] * nd + bb.z;
    float a3 = acc[3] * nd + bb.w;
    float m = fmaxf(fmaxf(a0, a1), fmaxf(a2, a3));
#pragma unroll
    for (int o = 8; o > 0; o >>= 1) m = fmaxf(m, __shfl_xor_sync(0xffffffffu, m, o));
    float e0 = __expf(a0 - m);
    float e1 = __expf(a1 - m);
    float e2 = __expf(a2 - m);
    float e3 = __expf(a3 - m);
    float s = e0 + e1 + e2 + e3;
#pragma unroll
    for (int o = 8; o > 0; o >>= 1) s += __shfl_xor_sync(0xffffffffu, s, o);
    float inv = 1.f / s;
    float4 o4 = make_float4(e0 * inv, e1 * inv, e2 * inv, e3 * inv);
    *reinterpret_cast<float4*>(out + (size_t)w * 64 + sl * 4) = o4;
}

// ---------------- launch ----------------

extern "C" void kernel_launch(void* const* d_in, const int* in_sizes, int n_in,
                              void* d_out, int out_size) {
    const float* x = (const float*)d_in[0];
    const int* src = (const int*)d_in[1];
    const int* dst = (const int*)d_in[2];
    const float* W0 = (const float*)d_in[3];
    const float* b0 = (const float*)d_in[4];
    const float* W1 = (const float*)d_in[5];
    const float* b1 = (const float*)d_in[6];
    const float* W2 = (const float*)d_in[7];
    const float* b2 = (const float*)d_in[8];
    float* out = (float*)d_out;

    __half *tmph, *hh;
    cudaGetSymbolAddress((void**)&tmph, g_tmph);
    cudaGetSymbolAddress((void**)&hh, g_hh);

    // one-time host objects (no device memory)
    static cudaStream_t s_side = nullptr;
    static cudaEvent_t s_fork = nullptr, s_join = nullptr;
    if (s_side == nullptr) {
        cudaStreamCreateWithFlags(&s_side, cudaStreamNonBlocking);
        cudaEventCreateWithFlags(&s_fork, cudaEventDisableTiming);
        cudaEventCreateWithFlags(&s_join, cudaEventDisableTiming);
    }

    const int TPB = 256;
    const int nodeBlocks = (N_NODES + TPB - 1) / TPB;
    const int edgeBlocks = (E_EDGES + TPB - 1) / TPB;
    const int nodeSub16Blocks = (int)(((size_t)N_NODES * 16 + TPB - 1) / TPB);

    // fork: layer-0 GEMM (unscaled — independent of degree/norms) on side stream
    cudaEventRecord(s_fork, 0);
    cudaStreamWaitEvent(s_side, s_fork, 0);
    gemm_h_k<NFEAT, NHID, false, float><<<N_NODES / 32, 128, 0, s_side>>>(x, W0, tmph);
    cudaEventRecord(s_join, s_side);

    // CSR build chain on main stream (concurrent with GEMM0)
    zero_deg_k<<<nodeBlocks, TPB>>>();
    degree_k<<<edgeBlocks, TPB>>>(src, dst);
    norms_k<<<nodeBlocks, TPB>>>();
    blocksum_k<<<SCAN_NB, 256>>>();
    scanblocks_k<<<1, 128>>>();
    localscan_k<<<SCAN_NB, 256>>>();
    scatter_k<<<edgeBlocks, TPB>>>(src, dst);

    // join
    cudaStreamWaitEvent(0, s_join, 0);

    // ---- Layer 0: SpMM applies n_src per gathered row ----
    spmm_csr128h_k<true><<<nodeSub16Blocks, TPB>>>(tmph, b0, hh);

    // ---- Layer 1: 128 -> 128 ----
    gemm_h_k<NHID, NHID, true, __half><<<N_NODES / 32, 128>>>(hh, W1, tmph);
    spmm_csr128h_k<false><<<nodeSub16Blocks, TPB>>>(tmph, b1, hh);

    // ---- Layer 2: 128 -> 64, + softmax ----
    gemm_h_k<NHID, NCLASS, true, __half><<<N_NODES / 32, 128>>>(hh, W2, tmph);
    spmm_csr64h_softmax_k<<<nodeSub16Blocks, TPB>>>(tmph, b2, out);
}

// round 12
// speedup vs baseline: 1.3923x; 1.3923x over previous
#include <cuda_runtime.h>
#include <cuda_bf16.h>
#include <cuda_fp16.h>
#include <math.h>

#define N_NODES 100000
#define E_EDGES 3200000
#define NFEAT 256
#define NHID 128
#define NCLASS 64

#define SCAN_CHUNK 1024
#define SCAN_NB ((N_NODES + SCAN_CHUNK - 1) / SCAN_CHUNK)   // 98

// Scratch (allocation-free rule: __device__ globals)
__device__ __align__(256) __half g_tmph[(size_t)N_NODES * NHID];   // fp16 activations
__device__ __align__(256) float g_h[(size_t)N_NODES * NHID];
__device__ __align__(256) float g_nsrc[N_NODES];
__device__ __align__(256) float g_ndst[N_NODES];
__device__ __align__(256) int g_degout[N_NODES];
__device__ __align__(256) int g_degin[N_NODES];
__device__ __align__(256) int g_rowptr[N_NODES + 1];
__device__ __align__(256) int g_cursor[N_NODES];
__device__ __align__(256) int g_csr[E_EDGES];
__device__ __align__(256) int g_blocksums[SCAN_NB];

// f32x2 helpers
__device__ __forceinline__ unsigned long long pack2(float lo, float hi) {
    unsigned long long r;
    asm("mov.b64 %0, {%1, %2};" : "=l"(r) : "f"(lo), "f"(hi));
    return r;
}
__device__ __forceinline__ void fma2(unsigned long long& acc,
                                     unsigned long long a,
                                     unsigned long long b) {
    asm("fma.rn.f32x2 %0, %1, %2, %0;" : "+l"(acc) : "l"(a), "l"(b));
}
__device__ __forceinline__ float2 unpack2(unsigned long long v) {
    float lo, hi;
    asm("mov.b64 {%0, %1}, %2;" : "=f"(lo), "=f"(hi) : "l"(v));
    return make_float2(lo, hi);
}
__device__ __forceinline__ float2 h2fu(unsigned u) {
    return __half22float2(*reinterpret_cast<__half2*>(&u));
}

// ---------------- degree / norms ----------------

__global__ void zero_deg_k() {
    int i = blockIdx.x * blockDim.x + threadIdx.x;
    if (i < N_NODES) { g_degout[i] = 0; g_degin[i] = 0; }
}

__global__ void degree_k(const int* __restrict__ src,
                         const int* __restrict__ dst) {
    int e = blockIdx.x * blockDim.x + threadIdx.x;
    if (e < E_EDGES) {
        atomicAdd(&g_degout[src[e]], 1);
        atomicAdd(&g_degin[dst[e]], 1);
    }
}

__global__ void norms_k() {
    int i = blockIdx.x * blockDim.x + threadIdx.x;
    if (i < N_NODES) {
        int dov = g_degout[i];
        int div_ = g_degin[i];
        g_nsrc[i] = rsqrtf((float)(dov > 0 ? dov : 1));
        g_ndst[i] = rsqrtf((float)(div_ > 0 ? div_ : 1));
    }
}

// ---------------- 3-phase exclusive scan of deg_in -> rowptr/cursor ----------------

__global__ void blocksum_k() {
    int base = blockIdx.x * SCAN_CHUNK;
    int tid = threadIdx.x;
    int s = 0;
#pragma unroll
    for (int j = 0; j < 4; j++) {
        int idx = base + tid * 4 + j;
        if (idx < N_NODES) s += g_degin[idx];
    }
#pragma unroll
    for (int o = 16; o > 0; o >>= 1) s += __shfl_xor_sync(0xffffffffu, s, o);
    __shared__ int ws[8];
    if ((tid & 31) == 0) ws[tid >> 5] = s;
    __syncthreads();
    if (tid == 0) {
        int t = 0;
#pragma unroll
        for (int w = 0; w < 8; w++) t += ws[w];
        g_blocksums[blockIdx.x] = t;
    }
}

__global__ void scanblocks_k() {
    __shared__ int s[128];
    int tid = threadIdx.x;
    int v = (tid < SCAN_NB) ? g_blocksums[tid] : 0;
    s[tid] = v;
    __syncthreads();
#pragma unroll
    for (int off = 1; off < 128; off <<= 1) {
        int t = (tid >= off) ? s[tid - off] : 0;
        __syncthreads();
        s[tid] += t;
        __syncthreads();
    }
    if (tid < SCAN_NB) g_blocksums[tid] = s[tid] - v;  // exclusive
}

__global__ void localscan_k() {
    int base = blockIdx.x * SCAN_CHUNK;
    int tid = threadIdx.x;
    int lane = tid & 31;
    int warp = tid >> 5;

    int e0 = base + tid * 4;
    int d0 = (e0 + 0 < N_NODES) ? g_degin[e0 + 0] : 0;
    int d1 = (e0 + 1 < N_NODES) ? g_degin[e0 + 1] : 0;
    int d2 = (e0 + 2 < N_NODES) ? g_degin[e0 + 2] : 0;
    int d3 = (e0 + 3 < N_NODES) ? g_degin[e0 + 3] : 0;
    int tsum = d0 + d1 + d2 + d3;

    int inc = tsum;
#pragma unroll
    for (int o = 1; o < 32; o <<= 1) {
        int t = __shfl_up_sync(0xffffffffu, inc, o);
        if (lane >= o) inc += t;
    }
    __shared__ int wsum[8];
    if (lane == 31) wsum[warp] = inc;
    __syncthreads();
    __shared__ int woff[8];
    if (tid == 0) {
        int acc = 0;
#pragma unroll
        for (int w = 0; w < 8; w++) { woff[w] = acc; acc += wsum[w]; }
    }
    __syncthreads();

    int thread_excl = g_blocksums[blockIdx.x] + woff[warp] + (inc - tsum);
    int p0 = thread_excl;
    int p1 = p0 + d0;
    int p2 = p1 + d1;
    int p3 = p2 + d2;
    if (e0 + 0 < N_NODES) { g_rowptr[e0 + 0] = p0; g_cursor[e0 + 0] = p0; }
    if (e0 + 1 < N_NODES) { g_rowptr[e0 + 1] = p1; g_cursor[e0 + 1] = p1; }
    if (e0 + 2 < N_NODES) { g_rowptr[e0 + 2] = p2; g_cursor[e0 + 2] = p2; }
    if (e0 + 3 < N_NODES) { g_rowptr[e0 + 3] = p3; g_cursor[e0 + 3] = p3; }
    if (blockIdx.x == 0 && tid == 0) g_rowptr[N_NODES] = E_EDGES;
}

__global__ void scatter_k(const int* __restrict__ src,
                          const int* __restrict__ dst) {
    int e = blockIdx.x * blockDim.x + threadIdx.x;
    if (e < E_EDGES) {
        int pos = atomicAdd(&g_cursor[dst[e]], 1);
        g_csr[pos] = src[e];
    }
}

// ---------------- GEMM: tmp16[i,j] = (sum_k H[i,k] W[k,j]) [* n_src[i] if SCALE] ------------
// fp32 accumulate (FFMA2), fp16 packed output. 128 threads, 32-row tile.
template <int IN, int OUT, bool SCALE>
__global__ void gemm_h_k(const float* __restrict__ H,
                         const float* __restrict__ W,
                         __half* __restrict__ out) {
    constexpr int CG = OUT / 4;     // col groups (thread handles 4 cols = 2 pairs)
    constexpr int RG = 128 / CG;    // row groups
    constexpr int R = 32 / RG;      // rows per thread
    __shared__ float Hs[32 * IN];

    int tid = threadIdx.x;
    int row0 = blockIdx.x * 32;

    {
        const float4* Hg = reinterpret_cast<const float4*>(H + (size_t)row0 * IN);
        float4* Hs4 = reinterpret_cast<float4*>(Hs);
#pragma unroll
        for (int i = tid; i < 32 * IN / 4; i += 128) Hs4[i] = Hg[i];
    }
    __syncthreads();

    int tx = tid % CG;
    int ty = tid / CG;
    const float* hbase = Hs + (size_t)(ty * R) * IN;

    unsigned long long acc[R][2];
#pragma unroll
    for (int r = 0; r < R; r++) { acc[r][0] = 0ull; acc[r][1] = 0ull; }

    for (int k = 0; k < IN; k += 2) {
        float4 w0 = *reinterpret_cast<const float4*>(W + (size_t)k * OUT + tx * 4);
        float4 w1 = *reinterpret_cast<const float4*>(W + (size_t)(k + 1) * OUT + tx * 4);
        unsigned long long w0a = pack2(w0.x, w0.y);
        unsigned long long w0b = pack2(w0.z, w0.w);
        unsigned long long w1a = pack2(w1.x, w1.y);
        unsigned long long w1b = pack2(w1.z, w1.w);
#pragma unroll
        for (int r = 0; r < R; r++) {
            float2 hv = *reinterpret_cast<const float2*>(hbase + (size_t)r * IN + k);
            unsigned long long hx = pack2(hv.x, hv.x);
            unsigned long long hy = pack2(hv.y, hv.y);
            fma2(acc[r][0], hx, w0a);
            fma2(acc[r][1], hx, w0b);
            fma2(acc[r][0], hy, w1a);
            fma2(acc[r][1], hy, w1b);
        }
    }

#pragma unroll
    for (int r = 0; r < R; r++) {
        int row = row0 + ty * R + r;
        float ns = SCALE ? g_nsrc[row] : 1.0f;
        float2 lo = unpack2(acc[r][0]);
        float2 hi = unpack2(acc[r][1]);
        __half2 p0 = __floats2half2_rn(lo.x * ns, lo.y * ns);
        __half2 p1 = __floats2half2_rn(hi.x * ns, hi.y * ns);
        uint2 st = make_uint2(*reinterpret_cast<unsigned*>(&p0),
                              *reinterpret_cast<unsigned*>(&p1));
        *reinterpret_cast<uint2*>(out + (size_t)row * OUT + tx * 4) = st;
    }
}

// ---------------- CSR SpMM (fp16 gather), fused finalize -----------------------------------
// warp per dst node, 4 halves (uint2) per lane for 128 features. fp32 accumulate.
// 8-edge unroll for MLP depth.
template <bool SRCSCALE>
__global__ void spmm_csr128h_k(const __half* __restrict__ tmp,
                               const float* __restrict__ b,
                               float* __restrict__ h) {
    int w = (blockIdx.x * blockDim.x + threadIdx.x) >> 5;
    int lane = threadIdx.x & 31;
    if (w >= N_NODES) return;
    int beg = g_rowptr[w];
    int end = g_rowptr[w + 1];
    float4 acc = make_float4(0.f, 0.f, 0.f, 0.f);
    int i = beg;
    for (; i + 7 < end; i += 8) {
        int s0 = g_csr[i], s1 = g_csr[i + 1], s2 = g_csr[i + 2], s3 = g_csr[i + 3];
        int s4 = g_csr[i + 4], s5 = g_csr[i + 5], s6 = g_csr[i + 6], s7 = g_csr[i + 7];
        uint2 u0 = *reinterpret_cast<const uint2*>(tmp + (size_t)s0 * 128 + lane * 4);
        uint2 u1 = *reinterpret_cast<const uint2*>(tmp + (size_t)s1 * 128 + lane * 4);
        uint2 u2 = *reinterpret_cast<const uint2*>(tmp + (size_t)s2 * 128 + lane * 4);
        uint2 u3 = *reinterpret_cast<const uint2*>(tmp + (size_t)s3 * 128 + lane * 4);
        uint2 u4 = *reinterpret_cast<const uint2*>(tmp + (size_t)s4 * 128 + lane * 4);
        uint2 u5 = *reinterpret_cast<const uint2*>(tmp + (size_t)s5 * 128 + lane * 4);
        uint2 u6 = *reinterpret_cast<const uint2*>(tmp + (size_t)s6 * 128 + lane * 4);
        uint2 u7 = *reinterpret_cast<const uint2*>(tmp + (size_t)s7 * 128 + lane * 4);
        float n0 = 1.f, n1 = 1.f, n2 = 1.f, n3 = 1.f;
        float n4 = 1.f, n5 = 1.f, n6 = 1.f, n7 = 1.f;
        if (SRCSCALE) {
            n0 = __ldg(&g_nsrc[s0]); n1 = __ldg(&g_nsrc[s1]);
            n2 = __ldg(&g_nsrc[s2]); n3 = __ldg(&g_nsrc[s3]);
            n4 = __ldg(&g_nsrc[s4]); n5 = __ldg(&g_nsrc[s5]);
            n6 = __ldg(&g_nsrc[s6]); n7 = __ldg(&g_nsrc[s7]);
        }
        float2 f;
        f = h2fu(u0.x); acc.x += f.x * n0; acc.y += f.y * n0;
        f = h2fu(u0.y); acc.z += f.x * n0; acc.w += f.y * n0;
        f = h2fu(u1.x); acc.x += f.x * n1; acc.y += f.y * n1;
        f = h2fu(u1.y); acc.z += f.x * n1; acc.w += f.y * n1;
        f = h2fu(u2.x); acc.x += f.x * n2; acc.y += f.y * n2;
        f = h2fu(u2.y); acc.z += f.x * n2; acc.w += f.y * n2;
        f = h2fu(u3.x); acc.x += f.x * n3; acc.y += f.y * n3;
        f = h2fu(u3.y); acc.z += f.x * n3; acc.w += f.y * n3;
        f = h2fu(u4.x); acc.x += f.x * n4; acc.y += f.y * n4;
        f = h2fu(u4.y); acc.z += f.x * n4; acc.w += f.y * n4;
        f = h2fu(u5.x); acc.x += f.x * n5; acc.y += f.y * n5;
        f = h2fu(u5.y); acc.z += f.x * n5; acc.w += f.y * n5;
        f = h2fu(u6.x); acc.x += f.x * n6; acc.y += f.y * n6;
        f = h2fu(u6.y); acc.z += f.x * n6; acc.w += f.y * n6;
        f = h2fu(u7.x); acc.x += f.x * n7; acc.y += f.y * n7;
        f = h2fu(u7.y); acc.z += f.x * n7; acc.w += f.y * n7;
    }
    for (; i < end; i++) {
        int s = g_csr[i];
        uint2 u = *reinterpret_cast<const uint2*>(tmp + (size_t)s * 128 + lane * 4);
        float ns = SRCSCALE ? __ldg(&g_nsrc[s]) : 1.0f;
        float2 f;
        f = h2fu(u.x); acc.x += f.x * ns; acc.y += f.y * ns;
        f = h2fu(u.y); acc.z += f.x * ns; acc.w += f.y * ns;
    }
    float nd = g_ndst[w];
    float4 bb = *reinterpret_cast<const float4*>(b + lane * 4);
    float4 o = make_float4(acc.x * nd + bb.x, acc.y * nd + bb.y,
                           acc.z * nd + bb.z, acc.w * nd + bb.w);
    *reinterpret_cast<float4*>(h + (size_t)w * 128 + lane * 4) = o;
}

// 64 features fp16 gather, fused finalize + softmax. warp per dst node, half2 per lane.
// 8-edge unroll.
__global__ void spmm_csr64h_softmax_k(const __half* __restrict__ tmp,
                                      const float* __restrict__ b,
                                      float* __restrict__ out) {
    int w = (blockIdx.x * blockDim.x + threadIdx.x) >> 5;
    int lane = threadIdx.x & 31;
    if (w >= N_NODES) return;
    int beg = g_rowptr[w];
    int end = g_rowptr[w + 1];
    float2 acc = make_float2(0.f, 0.f);
    int i = beg;
    for (; i + 7 < end; i += 8) {
        int s0 = g_csr[i], s1 = g_csr[i + 1], s2 = g_csr[i + 2], s3 = g_csr[i + 3];
        int s4 = g_csr[i + 4], s5 = g_csr[i + 5], s6 = g_csr[i + 6], s7 = g_csr[i + 7];
        unsigned v0 = *reinterpret_cast<const unsigned*>(tmp + (size_t)s0 * 64 + lane * 2);
        unsigned v1 = *reinterpret_cast<const unsigned*>(tmp + (size_t)s1 * 64 + lane * 2);
        unsigned v2 = *reinterpret_cast<const unsigned*>(tmp + (size_t)s2 * 64 + lane * 2);
        unsigned v3 = *reinterpret_cast<const unsigned*>(tmp + (size_t)s3 * 64 + lane * 2);
        unsigned v4 = *reinterpret_cast<const unsigned*>(tmp + (size_t)s4 * 64 + lane * 2);
        unsigned v5 = *reinterpret_cast<const unsigned*>(tmp + (size_t)s5 * 64 + lane * 2);
        unsigned v6 = *reinterpret_cast<const unsigned*>(tmp + (size_t)s6 * 64 + lane * 2);
        unsigned v7 = *reinterpret_cast<const unsigned*>(tmp + (size_t)s7 * 64 + lane * 2);
        float2 f;
        f = h2fu(v0); acc.x += f.x; acc.y += f.y;
        f = h2fu(v1); acc.x += f.x; acc.y += f.y;
        f = h2fu(v2); acc.x += f.x; acc.y += f.y;
        f = h2fu(v3); acc.x += f.x; acc.y += f.y;
        f = h2fu(v4); acc.x += f.x; acc.y += f.y;
        f = h2fu(v5); acc.x += f.x; acc.y += f.y;
        f = h2fu(v6); acc.x += f.x; acc.y += f.y;
        f = h2fu(v7); acc.x += f.x; acc.y += f.y;
    }
    for (; i < end; i++) {
        int s = g_csr[i];
        float2 f = h2fu(*reinterpret_cast<const unsigned*>(tmp + (size_t)s * 64 + lane * 2));
        acc.x += f.x; acc.y += f.y;
    }
    float nd = g_ndst[w];
    float2 bb = *reinterpret_cast<const float2*>(b + lane * 2);
    float a0 = acc.x * nd + bb.x;
    float a1 = acc.y * nd + bb.y;
    float m = fmaxf(a0, a1);
#pragma unroll
    for (int o = 16; o > 0; o >>= 1) m = fmaxf(m, __shfl_xor_sync(0xffffffffu, m, o));
    float e0 = __expf(a0 - m);
    float e1 = __expf(a1 - m);
    float s = e0 + e1;
#pragma unroll
    for (int o = 16; o > 0; o >>= 1) s += __shfl_xor_sync(0xffffffffu, s, o);
    float inv = 1.f / s;
    reinterpret_cast<float2*>(out + (size_t)w * 64)[lane] = make_float2(e0 * inv, e1 * inv);
}

// ---------------- launch ----------------

extern "C" void kernel_launch(void* const* d_in, const int* in_sizes, int n_in,
                              void* d_out, int out_size) {
    const float* x = (const float*)d_in[0];
    const int* src = (const int*)d_in[1];
    const int* dst = (const int*)d_in[2];
    const float* W0 = (const float*)d_in[3];
    const float* b0 = (const float*)d_in[4];
    const float* W1 = (const float*)d_in[5];
    const float* b1 = (const float*)d_in[6];
    const float* W2 = (const float*)d_in[7];
    const float* b2 = (const float*)d_in[8];
    float* out = (float*)d_out;

    __half* tmph;
    float* h;
    cudaGetSymbolAddress((void**)&tmph, g_tmph);
    cudaGetSymbolAddress((void**)&h, g_h);

    // one-time host objects (no device memory)
    static cudaStream_t s_side = nullptr;
    static cudaEvent_t s_fork = nullptr, s_join = nullptr;
    if (s_side == nullptr) {
        cudaStreamCreateWithFlags(&s_side, cudaStreamNonBlocking);
        cudaEventCreateWithFlags(&s_fork, cudaEventDisableTiming);
        cudaEventCreateWithFlags(&s_join, cudaEventDisableTiming);
    }

    const int TPB = 256;
    const int nodeBlocks = (N_NODES + TPB - 1) / TPB;
    const int edgeBlocks = (E_EDGES + TPB - 1) / TPB;
    const int nodeWarpBlocks = (int)(((size_t)N_NODES * 32 + TPB - 1) / TPB);

    // fork: layer-0 GEMM (unscaled — independent of degree/norms) on side stream
    cudaEventRecord(s_fork, 0);
    cudaStreamWaitEvent(s_side, s_fork, 0);
    gemm_h_k<NFEAT, NHID, false><<<N_NODES / 32, 128, 0, s_side>>>(x, W0, tmph);
    cudaEventRecord(s_join, s_side);

    // CSR build chain on main stream (concurrent with GEMM0)
    zero_deg_k<<<nodeBlocks, TPB>>>();
    degree_k<<<edgeBlocks, TPB>>>(src, dst);
    norms_k<<<nodeBlocks, TPB>>>();
    blocksum_k<<<SCAN_NB, 256>>>();
    scanblocks_k<<<1, 128>>>();
    localscan_k<<<SCAN_NB, 256>>>();
    scatter_k<<<edgeBlocks, TPB>>>(src, dst);

    // join
    cudaStreamWaitEvent(0, s_join, 0);

    // ---- Layer 0: SpMM applies n_src per gathered row ----
    spmm_csr128h_k<true><<<nodeWarpBlocks, TPB>>>(tmph, b0, h);

    // ---- Layer 1: 128 -> 128 ----
    gemm_h_k<NHID, NHID, true><<<N_NODES / 32, 128>>>(h, W1, tmph);
    spmm_csr128h_k<false><<<nodeWarpBlocks, TPB>>>(tmph, b1, h);

    // ---- Layer 2: 128 -> 64, + softmax ----
    gemm_h_k<NHID, NCLASS, true><<<N_NODES / 32, 128>>>(h, W2, tmph);
    spmm_csr64h_softmax_k<<<nodeWarpBlocks, TPB>>>(tmph, b2, out);
}

// round 13
// speedup vs baseline: 1.5557x; 1.1174x over previous
#include <cuda_runtime.h>
#include <cuda_bf16.h>
#include <cuda_fp16.h>
#include <mma.h>
#include <math.h>

using namespace nvcuda;

#define N_NODES 100000
#define N_PAD 100096          // 782 * 128
#define E_EDGES 3200000
#define NFEAT 256
#define NHID 128
#define NCLASS 64

#define SCAN_CHUNK 1024
#define SCAN_NB ((N_NODES + SCAN_CHUNK - 1) / SCAN_CHUNK)   // 98

// Scratch (allocation-free rule: __device__ globals; zero-initialized -> padding rows are 0)
__device__ __align__(256) __half g_xh[(size_t)N_PAD * NFEAT];     // x in fp16
__device__ __align__(256) __half g_tmph[(size_t)N_PAD * NHID];    // GEMM out (fp16)
__device__ __align__(256) __half g_hh[(size_t)N_PAD * NHID];      // SpMM out (fp16)
__device__ __align__(256) __half g_W0h[NFEAT * NHID];
__device__ __align__(256) __half g_W1h[NHID * NHID];
__device__ __align__(256) __half g_W2h[NHID * NCLASS];
__device__ __align__(256) float g_nsrc[N_NODES];
__device__ __align__(256) float g_ndst[N_NODES];
__device__ __align__(256) int g_degout[N_NODES];
__device__ __align__(256) int g_degin[N_NODES];
__device__ __align__(256) int g_rowptr[N_NODES + 1];
__device__ __align__(256) int g_cursor[N_NODES];
__device__ __align__(256) int g_csr[E_EDGES];
__device__ __align__(256) int g_blocksums[SCAN_NB];

__device__ __forceinline__ float2 h2fu(unsigned u) {
    return __half22float2(*reinterpret_cast<__half2*>(&u));
}

// ---------------- fp32 -> fp16 converters ----------------

__global__ void f2h4_k(const float4* __restrict__ src, uint2* __restrict__ dst, int n4) {
    int stride = gridDim.x * blockDim.x;
    for (int i = blockIdx.x * blockDim.x + threadIdx.x; i < n4; i += stride) {
        float4 v = src[i];
        __half2 h0 = __floats2half2_rn(v.x, v.y);
        __half2 h1 = __floats2half2_rn(v.z, v.w);
        dst[i] = make_uint2(*reinterpret_cast<unsigned*>(&h0),
                            *reinterpret_cast<unsigned*>(&h1));
    }
}

// ---------------- degree / norms ----------------

__global__ void zero_deg_k() {
    int i = blockIdx.x * blockDim.x + threadIdx.x;
    if (i < N_NODES) { g_degout[i] = 0; g_degin[i] = 0; }
}

__global__ void degree_k(const int* __restrict__ src,
                         const int* __restrict__ dst) {
    int e = blockIdx.x * blockDim.x + threadIdx.x;
    if (e < E_EDGES) {
        atomicAdd(&g_degout[src[e]], 1);
        atomicAdd(&g_degin[dst[e]], 1);
    }
}

__global__ void norms_k() {
    int i = blockIdx.x * blockDim.x + threadIdx.x;
    if (i < N_NODES) {
        int dov = g_degout[i];
        int div_ = g_degin[i];
        g_nsrc[i] = rsqrtf((float)(dov > 0 ? dov : 1));
        g_ndst[i] = rsqrtf((float)(div_ > 0 ? div_ : 1));
    }
}

// ---------------- 3-phase exclusive scan of deg_in -> rowptr/cursor ----------------

__global__ void blocksum_k() {
    int base = blockIdx.x * SCAN_CHUNK;
    int tid = threadIdx.x;
    int s = 0;
#pragma unroll
    for (int j = 0; j < 4; j++) {
        int idx = base + tid * 4 + j;
        if (idx < N_NODES) s += g_degin[idx];
    }
#pragma unroll
    for (int o = 16; o > 0; o >>= 1) s += __shfl_xor_sync(0xffffffffu, s, o);
    __shared__ int ws[8];
    if ((tid & 31) == 0) ws[tid >> 5] = s;
    __syncthreads();
    if (tid == 0) {
        int t = 0;
#pragma unroll
        for (int w = 0; w < 8; w++) t += ws[w];
        g_blocksums[blockIdx.x] = t;
    }
}

__global__ void scanblocks_k() {
    __shared__ int s[128];
    int tid = threadIdx.x;
    int v = (tid < SCAN_NB) ? g_blocksums[tid] : 0;
    s[tid] = v;
    __syncthreads();
#pragma unroll
    for (int off = 1; off < 128; off <<= 1) {
        int t = (tid >= off) ? s[tid - off] : 0;
        __syncthreads();
        s[tid] += t;
        __syncthreads();
    }
    if (tid < SCAN_NB) g_blocksums[tid] = s[tid] - v;  // exclusive
}

__global__ void localscan_k() {
    int base = blockIdx.x * SCAN_CHUNK;
    int tid = threadIdx.x;
    int lane = tid & 31;
    int warp = tid >> 5;

    int e0 = base + tid * 4;
    int d0 = (e0 + 0 < N_NODES) ? g_degin[e0 + 0] : 0;
    int d1 = (e0 + 1 < N_NODES) ? g_degin[e0 + 1] : 0;
    int d2 = (e0 + 2 < N_NODES) ? g_degin[e0 + 2] : 0;
    int d3 = (e0 + 3 < N_NODES) ? g_degin[e0 + 3] : 0;
    int tsum = d0 + d1 + d2 + d3;

    int inc = tsum;
#pragma unroll
    for (int o = 1; o < 32; o <<= 1) {
        int t = __shfl_up_sync(0xffffffffu, inc, o);
        if (lane >= o) inc += t;
    }
    __shared__ int wsum[8];
    if (lane == 31) wsum[warp] = inc;
    __syncthreads();
    __shared__ int woff[8];
    if (tid == 0) {
        int acc = 0;
#pragma unroll
        for (int w = 0; w < 8; w++) { woff[w] = acc; acc += wsum[w]; }
    }
    __syncthreads();

    int thread_excl = g_blocksums[blockIdx.x] + woff[warp] + (inc - tsum);
    int p0 = thread_excl;
    int p1 = p0 + d0;
    int p2 = p1 + d1;
    int p3 = p2 + d2;
    if (e0 + 0 < N_NODES) { g_rowptr[e0 + 0] = p0; g_cursor[e0 + 0] = p0; }
    if (e0 + 1 < N_NODES) { g_rowptr[e0 + 1] = p1; g_cursor[e0 + 1] = p1; }
    if (e0 + 2 < N_NODES) { g_rowptr[e0 + 2] = p2; g_cursor[e0 + 2] = p2; }
    if (e0 + 3 < N_NODES) { g_rowptr[e0 + 3] = p3; g_cursor[e0 + 3] = p3; }
    if (blockIdx.x == 0 && tid == 0) g_rowptr[N_NODES] = E_EDGES;
}

__global__ void scatter_k(const int* __restrict__ src,
                          const int* __restrict__ dst) {
    int e = blockIdx.x * blockDim.x + threadIdx.x;
    if (e < E_EDGES) {
        int pos = atomicAdd(&g_cursor[dst[e]], 1);
        g_csr[pos] = src[e];
    }
}

// ---------------- WMMA GEMM: C[i,j] = sum_k A[i,k] B[k,j]  (half x half -> fp32 -> half) ----
// 256 threads = 8 warps (4 row-groups x 2 col-groups). Block tile 128 x OUT.
// Warp tile 32 x OUT/2 = 2 x (OUT/32) fragments of 16x16.
template <int IN, int OUT>
__global__ void gemm_wmma_k(const __half* __restrict__ A,
                            const __half* __restrict__ B,   // [IN][OUT] row-major
                            __half* __restrict__ C) {       // [N_PAD][OUT]
    constexpr int FC = OUT / 32;
    __shared__ float stage[8][256];

    int wid = threadIdx.x >> 5;
    int lane = threadIdx.x & 31;
    int wr = wid >> 1;
    int wc = wid & 1;
    int row0 = blockIdx.x * 128 + wr * 32;
    int col0 = wc * (OUT / 2);

    wmma::fragment<wmma::accumulator, 16, 16, 16, float> acc[2][FC];
#pragma unroll
    for (int i = 0; i < 2; i++)
#pragma unroll
        for (int j = 0; j < FC; j++)
            wmma::fill_fragment(acc[i][j], 0.0f);

    for (int k = 0; k < IN; k += 16) {
        wmma::fragment<wmma::matrix_a, 16, 16, 16, __half, wmma::row_major> af0, af1;
        wmma::load_matrix_sync(af0, A + (size_t)row0 * IN + k, IN);
        wmma::load_matrix_sync(af1, A + (size_t)(row0 + 16) * IN + k, IN);
#pragma unroll
        for (int j = 0; j < FC; j++) {
            wmma::fragment<wmma::matrix_b, 16, 16, 16, __half, wmma::row_major> bf;
            wmma::load_matrix_sync(bf, B + (size_t)k * OUT + col0 + j * 16, OUT);
            wmma::mma_sync(acc[0][j], af0, bf, acc[0][j]);
            wmma::mma_sync(acc[1][j], af1, bf, acc[1][j]);
        }
    }

    // epilogue: per-warp smem staging, convert to half, vectorized store
#pragma unroll
    for (int i = 0; i < 2; i++)
#pragma unroll
        for (int j = 0; j < FC; j++) {
            wmma::store_matrix_sync(stage[wid], acc[i][j], 16, wmma::mem_row_major);
            __syncwarp();
            const float* sp = stage[wid] + (lane >> 1) * 16 + (lane & 1) * 8;
            __half2 h0 = __floats2half2_rn(sp[0], sp[1]);
            __half2 h1 = __floats2half2_rn(sp[2], sp[3]);
            __half2 h2 = __floats2half2_rn(sp[4], sp[5]);
            __half2 h3 = __floats2half2_rn(sp[6], sp[7]);
            uint4 st = make_uint4(*reinterpret_cast<unsigned*>(&h0),
                                  *reinterpret_cast<unsigned*>(&h1),
                                  *reinterpret_cast<unsigned*>(&h2),
                                  *reinterpret_cast<unsigned*>(&h3));
            size_t off = (size_t)(row0 + i * 16 + (lane >> 1)) * OUT
                       + col0 + j * 16 + (lane & 1) * 8;
            *reinterpret_cast<uint4*>(C + off) = st;
            __syncwarp();
        }
}

// ---------------- CSR SpMM (fp16 gather), fused n_src + finalize, fp16 out ----------------
// warp per dst node, 4 halves (uint2) per lane for 128 features. fp32 accumulate.
__global__ void spmm_csr128h_k(const __half* __restrict__ tmp,
                               const float* __restrict__ b,
                               __half* __restrict__ h) {
    int w = (blockIdx.x * blockDim.x + threadIdx.x) >> 5;
    int lane = threadIdx.x & 31;
    if (w >= N_NODES) return;
    int beg = g_rowptr[w];
    int end = g_rowptr[w + 1];
    float4 acc = make_float4(0.f, 0.f, 0.f, 0.f);
    int i = beg;
    for (; i + 7 < end; i += 8) {
        int s0 = g_csr[i], s1 = g_csr[i + 1], s2 = g_csr[i + 2], s3 = g_csr[i + 3];
        int s4 = g_csr[i + 4], s5 = g_csr[i + 5], s6 = g_csr[i + 6], s7 = g_csr[i + 7];
        uint2 u0 = *reinterpret_cast<const uint2*>(tmp + (size_t)s0 * 128 + lane * 4);
        uint2 u1 = *reinterpret_cast<const uint2*>(tmp + (size_t)s1 * 128 + lane * 4);
        uint2 u2 = *reinterpret_cast<const uint2*>(tmp + (size_t)s2 * 128 + lane * 4);
        uint2 u3 = *reinterpret_cast<const uint2*>(tmp + (size_t)s3 * 128 + lane * 4);
        uint2 u4 = *reinterpret_cast<const uint2*>(tmp + (size_t)s4 * 128 + lane * 4);
        uint2 u5 = *reinterpret_cast<const uint2*>(tmp + (size_t)s5 * 128 + lane * 4);
        uint2 u6 = *reinterpret_cast<const uint2*>(tmp + (size_t)s6 * 128 + lane * 4);
        uint2 u7 = *reinterpret_cast<const uint2*>(tmp + (size_t)s7 * 128 + lane * 4);
        float n0 = __ldg(&g_nsrc[s0]), n1 = __ldg(&g_nsrc[s1]);
        float n2 = __ldg(&g_nsrc[s2]), n3 = __ldg(&g_nsrc[s3]);
        float n4 = __ldg(&g_nsrc[s4]), n5 = __ldg(&g_nsrc[s5]);
        float n6 = __ldg(&g_nsrc[s6]), n7 = __ldg(&g_nsrc[s7]);
        float2 f;
        f = h2fu(u0.x); acc.x += f.x * n0; acc.y += f.y * n0;
        f = h2fu(u0.y); acc.z += f.x * n0; acc.w += f.y * n0;
        f = h2fu(u1.x); acc.x += f.x * n1; acc.y += f.y * n1;
        f = h2fu(u1.y); acc.z += f.x * n1; acc.w += f.y * n1;
        f = h2fu(u2.x); acc.x += f.x * n2; acc.y += f.y * n2;
        f = h2fu(u2.y); acc.z += f.x * n2; acc.w += f.y * n2;
        f = h2fu(u3.x); acc.x += f.x * n3; acc.y += f.y * n3;
        f = h2fu(u3.y); acc.z += f.x * n3; acc.w += f.y * n3;
        f = h2fu(u4.x); acc.x += f.x * n4; acc.y += f.y * n4;
        f = h2fu(u4.y); acc.z += f.x * n4; acc.w += f.y * n4;
        f = h2fu(u5.x); acc.x += f.x * n5; acc.y += f.y * n5;
        f = h2fu(u5.y); acc.z += f.x * n5; acc.w += f.y * n5;
        f = h2fu(u6.x); acc.x += f.x * n6; acc.y += f.y * n6;
        f = h2fu(u6.y); acc.z += f.x * n6; acc.w += f.y * n6;
        f = h2fu(u7.x); acc.x += f.x * n7; acc.y += f.y * n7;
        f = h2fu(u7.y); acc.z += f.x * n7; acc.w += f.y * n7;
    }
    for (; i < end; i++) {
        int s = g_csr[i];
        uint2 u = *reinterpret_cast<const uint2*>(tmp + (size_t)s * 128 + lane * 4);
        float ns = __ldg(&g_nsrc[s]);
        float2 f;
        f = h2fu(u.x); acc.x += f.x * ns; acc.y += f.y * ns;
        f = h2fu(u.y); acc.z += f.x * ns; acc.w += f.y * ns;
    }
    float nd = g_ndst[w];
    float4 bb = *reinterpret_cast<const float4*>(b + lane * 4);
    __half2 p0 = __floats2half2_rn(acc.x * nd + bb.x, acc.y * nd + bb.y);
    __half2 p1 = __floats2half2_rn(acc.z * nd + bb.z, acc.w * nd + bb.w);
    uint2 st = make_uint2(*reinterpret_cast<unsigned*>(&p0),
                          *reinterpret_cast<unsigned*>(&p1));
    *reinterpret_cast<uint2*>(h + (size_t)w * 128 + lane * 4) = st;
}

// 64 features fp16 gather + n_src, fused finalize + softmax. warp per node, half2 per lane.
__global__ void spmm_csr64h_softmax_k(const __half* __restrict__ tmp,
                                      const float* __restrict__ b,
                                      float* __restrict__ out) {
    int w = (blockIdx.x * blockDim.x + threadIdx.x) >> 5;
    int lane = threadIdx.x & 31;
    if (w >= N_NODES) return;
    int beg = g_rowptr[w];
    int end = g_rowptr[w + 1];
    float2 acc = make_float2(0.f, 0.f);
    int i = beg;
    for (; i + 7 < end; i += 8) {
        int s0 = g_csr[i], s1 = g_csr[i + 1], s2 = g_csr[i + 2], s3 = g_csr[i + 3];
        int s4 = g_csr[i + 4], s5 = g_csr[i + 5], s6 = g_csr[i + 6], s7 = g_csr[i + 7];
        unsigned v0 = *reinterpret_cast<const unsigned*>(tmp + (size_t)s0 * 64 + lane * 2);
        unsigned v1 = *reinterpret_cast<const unsigned*>(tmp + (size_t)s1 * 64 + lane * 2);
        unsigned v2 = *reinterpret_cast<const unsigned*>(tmp + (size_t)s2 * 64 + lane * 2);
        unsigned v3 = *reinterpret_cast<const unsigned*>(tmp + (size_t)s3 * 64 + lane * 2);
        unsigned v4 = *reinterpret_cast<const unsigned*>(tmp + (size_t)s4 * 64 + lane * 2);
        unsigned v5 = *reinterpret_cast<const unsigned*>(tmp + (size_t)s5 * 64 + lane * 2);
        unsigned v6 = *reinterpret_cast<const unsigned*>(tmp + (size_t)s6 * 64 + lane * 2);
        unsigned v7 = *reinterpret_cast<const unsigned*>(tmp + (size_t)s7 * 64 + lane * 2);
        float n0 = __ldg(&g_nsrc[s0]), n1 = __ldg(&g_nsrc[s1]);
        float n2 = __ldg(&g_nsrc[s2]), n3 = __ldg(&g_nsrc[s3]);
        float n4 = __ldg(&g_nsrc[s4]), n5 = __ldg(&g_nsrc[s5]);
        float n6 = __ldg(&g_nsrc[s6]), n7 = __ldg(&g_nsrc[s7]);
        float2 f;
        f = h2fu(v0); acc.x += f.x * n0; acc.y += f.y * n0;
        f = h2fu(v1); acc.x += f.x * n1; acc.y += f.y * n1;
        f = h2fu(v2); acc.x += f.x * n2; acc.y += f.y * n2;
        f = h2fu(v3); acc.x += f.x * n3; acc.y += f.y * n3;
        f = h2fu(v4); acc.x += f.x * n4; acc.y += f.y * n4;
        f = h2fu(v5); acc.x += f.x * n5; acc.y += f.y * n5;
        f = h2fu(v6); acc.x += f.x * n6; acc.y += f.y * n6;
        f = h2fu(v7); acc.x += f.x * n7; acc.y += f.y * n7;
    }
    for (; i < end; i++) {
        int s = g_csr[i];
        float ns = __ldg(&g_nsrc[s]);
        float2 f = h2fu(*reinterpret_cast<const unsigned*>(tmp + (size_t)s * 64 + lane * 2));
        acc.x += f.x * ns; acc.y += f.y * ns;
    }
    float nd = g_ndst[w];
    float2 bb = *reinterpret_cast<const float2*>(b + lane * 2);
    float a0 = acc.x * nd + bb.x;
    float a1 = acc.y * nd + bb.y;
    float m = fmaxf(a0, a1);
#pragma unroll
    for (int o = 16; o > 0; o >>= 1) m = fmaxf(m, __shfl_xor_sync(0xffffffffu, m, o));
    float e0 = __expf(a0 - m);
    float e1 = __expf(a1 - m);
    float s = e0 + e1;
#pragma unroll
    for (int o = 16; o > 0; o >>= 1) s += __shfl_xor_sync(0xffffffffu, s, o);
    float inv = 1.f / s;
    reinterpret_cast<float2*>(out + (size_t)w * 64)[lane] = make_float2(e0 * inv, e1 * inv);
}

// ---------------- launch ----------------

extern "C" void kernel_launch(void* const* d_in, const int* in_sizes, int n_in,
                              void* d_out, int out_size) {
    const float* x = (const float*)d_in[0];
    const int* src = (const int*)d_in[1];
    const int* dst = (const int*)d_in[2];
    const float* W0 = (const float*)d_in[3];
    const float* b0 = (const float*)d_in[4];
    const float* W1 = (const float*)d_in[5];
    const float* b1 = (const float*)d_in[6];
    const float* W2 = (const float*)d_in[7];
    const float* b2 = (const float*)d_in[8];
    float* out = (float*)d_out;

    __half *xh, *tmph, *hh, *w0h, *w1h, *w2h;
    cudaGetSymbolAddress((void**)&xh, g_xh);
    cudaGetSymbolAddress((void**)&tmph, g_tmph);
    cudaGetSymbolAddress((void**)&hh, g_hh);
    cudaGetSymbolAddress((void**)&w0h, g_W0h);
    cudaGetSymbolAddress((void**)&w1h, g_W1h);
    cudaGetSymbolAddress((void**)&w2h, g_W2h);

    // one-time host objects (no device memory)
    static cudaStream_t s_side = nullptr;
    static cudaEvent_t s_fork = nullptr, s_join = nullptr;
    if (s_side == nullptr) {
        cudaStreamCreateWithFlags(&s_side, cudaStreamNonBlocking);
        cudaEventCreateWithFlags(&s_fork, cudaEventDisableTiming);
        cudaEventCreateWithFlags(&s_join, cudaEventDisableTiming);
    }

    const int TPB = 256;
    const int nodeBlocks = (N_NODES + TPB - 1) / TPB;
    const int edgeBlocks = (E_EDGES + TPB - 1) / TPB;
    const int nodeWarpBlocks = (int)(((size_t)N_NODES * 32 + TPB - 1) / TPB);
    const int gemmBlocks = N_PAD / 128;   // 782

    // fork: fp16 conversions + layer-0 GEMM on side stream (independent of CSR build)
    cudaEventRecord(s_fork, 0);
    cudaStreamWaitEvent(s_side, s_fork, 0);
    f2h4_k<<<2048, TPB, 0, s_side>>>((const float4*)x, (uint2*)xh, N_NODES * NFEAT / 4);
    f2h4_k<<<32, TPB, 0, s_side>>>((const float4*)W0, (uint2*)w0h, NFEAT * NHID / 4);
    f2h4_k<<<16, TPB, 0, s_side>>>((const float4*)W1, (uint2*)w1h, NHID * NHID / 4);
    f2h4_k<<<8, TPB, 0, s_side>>>((const float4*)W2, (uint2*)w2h, NHID * NCLASS / 4);
    gemm_wmma_k<NFEAT, NHID><<<gemmBlocks, 256, 0, s_side>>>(xh, w0h, tmph);
    cudaEventRecord(s_join, s_side);

    // CSR build chain on main stream (concurrent with conversions + GEMM0)
    zero_deg_k<<<nodeBlocks, TPB>>>();
    degree_k<<<edgeBlocks, TPB>>>(src, dst);
    norms_k<<<nodeBlocks, TPB>>>();
    blocksum_k<<<SCAN_NB, 256>>>();
    scanblocks_k<<<1, 128>>>();
    localscan_k<<<SCAN_NB, 256>>>();
    scatter_k<<<edgeBlocks, TPB>>>(src, dst);

    // join
    cudaStreamWaitEvent(0, s_join, 0);

    // ---- Layer 0 ----
    spmm_csr128h_k<<<nodeWarpBlocks, TPB>>>(tmph, b0, hh);

    // ---- Layer 1: 128 -> 128 ----
    gemm_wmma_k<NHID, NHID><<<gemmBlocks, 256>>>(hh, w1h, tmph);
    spmm_csr128h_k<<<nodeWarpBlocks, TPB>>>(tmph, b1, hh);

    // ---- Layer 2: 128 -> 64, + softmax ----
    gemm_wmma_k<NHID, NCLASS><<<gemmBlocks, 256>>>(hh, w2h, tmph);
    spmm_csr64h_softmax_k<<<nodeWarpBlocks, TPB>>>(tmph, b2, out);
}

// round 14
// speedup vs baseline: 1.5645x; 1.0057x over previous
#include <cuda_runtime.h>
#include <cuda_bf16.h>
#include <cuda_fp16.h>
#include <mma.h>
#include <math.h>

using namespace nvcuda;

#define N_NODES 100000
#define N_PAD 100096          // 782 * 128
#define E_EDGES 3200000
#define NFEAT 256
#define NHID 128
#define NCLASS 64

#define SCAN_CHUNK 1024
#define SCAN_NB ((N_NODES + SCAN_CHUNK - 1) / SCAN_CHUNK)   // 98

// Scratch (allocation-free rule: __device__ globals; zero-initialized -> padding rows are 0)
__device__ __align__(256) __half g_xh[(size_t)N_PAD * NFEAT];     // x in fp16
__device__ __align__(256) __half g_tmph[(size_t)N_PAD * NHID];    // GEMM out (fp16)
__device__ __align__(256) __half g_hh[(size_t)N_PAD * NHID];      // SpMM out (fp16)
__device__ __align__(256) __half g_W0h[NFEAT * NHID];
__device__ __align__(256) __half g_W1h[NHID * NHID];
__device__ __align__(256) __half g_W2h[NHID * NCLASS];
__device__ __align__(256) float g_nsrc[N_NODES];
__device__ __align__(256) float g_ndst[N_NODES];
__device__ __align__(256) int g_degout[N_NODES];
__device__ __align__(256) int g_degin[N_NODES];
__device__ __align__(256) int g_rowptr[N_NODES + 1];
__device__ __align__(256) int g_cursor[N_NODES];
__device__ __align__(256) int g_csr[E_EDGES];
__device__ __align__(256) int g_blocksums[SCAN_NB];

__device__ __forceinline__ float2 h2fu(unsigned u) {
    return __half22float2(*reinterpret_cast<__half2*>(&u));
}

// ---------------- fp32 -> fp16 converters ----------------

__global__ void f2h4_k(const float4* __restrict__ src, uint2* __restrict__ dst, int n4) {
    int stride = gridDim.x * blockDim.x;
    for (int i = blockIdx.x * blockDim.x + threadIdx.x; i < n4; i += stride) {
        float4 v = src[i];
        __half2 h0 = __floats2half2_rn(v.x, v.y);
        __half2 h1 = __floats2half2_rn(v.z, v.w);
        dst[i] = make_uint2(*reinterpret_cast<unsigned*>(&h0),
                            *reinterpret_cast<unsigned*>(&h1));
    }
}

// ---------------- degree / norms ----------------

__global__ void zero_deg_k() {
    int i = blockIdx.x * blockDim.x + threadIdx.x;
    if (i < N_NODES) { g_degout[i] = 0; g_degin[i] = 0; }
}

// 2 edges per thread, int2 loads
__global__ void degree_k(const int2* __restrict__ src2,
                         const int2* __restrict__ dst2) {
    int e = blockIdx.x * blockDim.x + threadIdx.x;
    if (e < E_EDGES / 2) {
        int2 s = src2[e];
        int2 d = dst2[e];
        atomicAdd(&g_degout[s.x], 1);
        atomicAdd(&g_degout[s.y], 1);
        atomicAdd(&g_degin[d.x], 1);
        atomicAdd(&g_degin[d.y], 1);
    }
}

__global__ void norms_k() {
    int i = blockIdx.x * blockDim.x + threadIdx.x;
    if (i < N_NODES) {
        int dov = g_degout[i];
        int div_ = g_degin[i];
        g_nsrc[i] = rsqrtf((float)(dov > 0 ? dov : 1));
        g_ndst[i] = rsqrtf((float)(div_ > 0 ? div_ : 1));
    }
}

// ---------------- 3-phase exclusive scan of deg_in -> rowptr/cursor ----------------

__global__ void blocksum_k() {
    int base = blockIdx.x * SCAN_CHUNK;
    int tid = threadIdx.x;
    int s = 0;
#pragma unroll
    for (int j = 0; j < 4; j++) {
        int idx = base + tid * 4 + j;
        if (idx < N_NODES) s += g_degin[idx];
    }
#pragma unroll
    for (int o = 16; o > 0; o >>= 1) s += __shfl_xor_sync(0xffffffffu, s, o);
    __shared__ int ws[8];
    if ((tid & 31) == 0) ws[tid >> 5] = s;
    __syncthreads();
    if (tid == 0) {
        int t = 0;
#pragma unroll
        for (int w = 0; w < 8; w++) t += ws[w];
        g_blocksums[blockIdx.x] = t;
    }
}

__global__ void scanblocks_k() {
    __shared__ int s[128];
    int tid = threadIdx.x;
    int v = (tid < SCAN_NB) ? g_blocksums[tid] : 0;
    s[tid] = v;
    __syncthreads();
#pragma unroll
    for (int off = 1; off < 128; off <<= 1) {
        int t = (tid >= off) ? s[tid - off] : 0;
        __syncthreads();
        s[tid] += t;
        __syncthreads();
    }
    if (tid < SCAN_NB) g_blocksums[tid] = s[tid] - v;  // exclusive
}

__global__ void localscan_k() {
    int base = blockIdx.x * SCAN_CHUNK;
    int tid = threadIdx.x;
    int lane = tid & 31;
    int warp = tid >> 5;

    int e0 = base + tid * 4;
    int d0 = (e0 + 0 < N_NODES) ? g_degin[e0 + 0] : 0;
    int d1 = (e0 + 1 < N_NODES) ? g_degin[e0 + 1] : 0;
    int d2 = (e0 + 2 < N_NODES) ? g_degin[e0 + 2] : 0;
    int d3 = (e0 + 3 < N_NODES) ? g_degin[e0 + 3] : 0;
    int tsum = d0 + d1 + d2 + d3;

    int inc = tsum;
#pragma unroll
    for (int o = 1; o < 32; o <<= 1) {
        int t = __shfl_up_sync(0xffffffffu, inc, o);
        if (lane >= o) inc += t;
    }
    __shared__ int wsum[8];
    if (lane == 31) wsum[warp] = inc;
    __syncthreads();
    __shared__ int woff[8];
    if (tid == 0) {
        int acc = 0;
#pragma unroll
        for (int w = 0; w < 8; w++) { woff[w] = acc; acc += wsum[w]; }
    }
    __syncthreads();

    int thread_excl = g_blocksums[blockIdx.x] + woff[warp] + (inc - tsum);
    int p0 = thread_excl;
    int p1 = p0 + d0;
    int p2 = p1 + d1;
    int p3 = p2 + d2;
    if (e0 + 0 < N_NODES) { g_rowptr[e0 + 0] = p0; g_cursor[e0 + 0] = p0; }
    if (e0 + 1 < N_NODES) { g_rowptr[e0 + 1] = p1; g_cursor[e0 + 1] = p1; }
    if (e0 + 2 < N_NODES) { g_rowptr[e0 + 2] = p2; g_cursor[e0 + 2] = p2; }
    if (e0 + 3 < N_NODES) { g_rowptr[e0 + 3] = p3; g_cursor[e0 + 3] = p3; }
    if (blockIdx.x == 0 && tid == 0) g_rowptr[N_NODES] = E_EDGES;
}

// 4 edges per thread, int4 loads
__global__ void scatter_k(const int4* __restrict__ src4,
                          const int4* __restrict__ dst4) {
    int e = blockIdx.x * blockDim.x + threadIdx.x;
    if (e < E_EDGES / 4) {
        int4 s = src4[e];
        int4 d = dst4[e];
        g_csr[atomicAdd(&g_cursor[d.x], 1)] = s.x;
        g_csr[atomicAdd(&g_cursor[d.y], 1)] = s.y;
        g_csr[atomicAdd(&g_cursor[d.z], 1)] = s.z;
        g_csr[atomicAdd(&g_cursor[d.w], 1)] = s.w;
    }
}

// ---------------- WMMA GEMM: C[i,j] = sum_k A[i,k] B[k,j]  (half x half -> fp32 -> half) ----
// 256 threads = 8 warps (4 row-groups x 2 col-groups). Block tile 128 x OUT.
template <int IN, int OUT>
__global__ void gemm_wmma_k(const __half* __restrict__ A,
                            const __half* __restrict__ B,   // [IN][OUT] row-major
                            __half* __restrict__ C) {       // [N_PAD][OUT]
    constexpr int FC = OUT / 32;
    __shared__ float stage[8][256];

    int wid = threadIdx.x >> 5;
    int lane = threadIdx.x & 31;
    int wr = wid >> 1;
    int wc = wid & 1;
    int row0 = blockIdx.x * 128 + wr * 32;
    int col0 = wc * (OUT / 2);

    wmma::fragment<wmma::accumulator, 16, 16, 16, float> acc[2][FC];
#pragma unroll
    for (int i = 0; i < 2; i++)
#pragma unroll
        for (int j = 0; j < FC; j++)
            wmma::fill_fragment(acc[i][j], 0.0f);

    for (int k = 0; k < IN; k += 16) {
        wmma::fragment<wmma::matrix_a, 16, 16, 16, __half, wmma::row_major> af0, af1;
        wmma::load_matrix_sync(af0, A + (size_t)row0 * IN + k, IN);
        wmma::load_matrix_sync(af1, A + (size_t)(row0 + 16) * IN + k, IN);
#pragma unroll
        for (int j = 0; j < FC; j++) {
            wmma::fragment<wmma::matrix_b, 16, 16, 16, __half, wmma::row_major> bf;
            wmma::load_matrix_sync(bf, B + (size_t)k * OUT + col0 + j * 16, OUT);
            wmma::mma_sync(acc[0][j], af0, bf, acc[0][j]);
            wmma::mma_sync(acc[1][j], af1, bf, acc[1][j]);
        }
    }

#pragma unroll
    for (int i = 0; i < 2; i++)
#pragma unroll
        for (int j = 0; j < FC; j++) {
            wmma::store_matrix_sync(stage[wid], acc[i][j], 16, wmma::mem_row_major);
            __syncwarp();
            const float* sp = stage[wid] + (lane >> 1) * 16 + (lane & 1) * 8;
            __half2 h0 = __floats2half2_rn(sp[0], sp[1]);
            __half2 h1 = __floats2half2_rn(sp[2], sp[3]);
            __half2 h2 = __floats2half2_rn(sp[4], sp[5]);
            __half2 h3 = __floats2half2_rn(sp[6], sp[7]);
            uint4 st = make_uint4(*reinterpret_cast<unsigned*>(&h0),
                                  *reinterpret_cast<unsigned*>(&h1),
                                  *reinterpret_cast<unsigned*>(&h2),
                                  *reinterpret_cast<unsigned*>(&h3));
            size_t off = (size_t)(row0 + i * 16 + (lane >> 1)) * OUT
                       + col0 + j * 16 + (lane & 1) * 8;
            *reinterpret_cast<uint4*>(C + off) = st;
            __syncwarp();
        }
}

// ---------------- CSR SpMM (fp16 gather), fused n_src + finalize, fp16 out ----------------
// warp per dst node, 4 halves (uint2) per lane for 128 features. fp32 accumulate.
// 16-edge unroll for MLP depth.
__global__ void spmm_csr128h_k(const __half* __restrict__ tmp,
                               const float* __restrict__ b,
                               __half* __restrict__ h) {
    int w = (blockIdx.x * blockDim.x + threadIdx.x) >> 5;
    int lane = threadIdx.x & 31;
    if (w >= N_NODES) return;
    int beg = g_rowptr[w];
    int end = g_rowptr[w + 1];
    float4 acc = make_float4(0.f, 0.f, 0.f, 0.f);
    int i = beg;
    for (; i + 15 < end; i += 16) {
        int s[16];
#pragma unroll
        for (int j = 0; j < 16; j++) s[j] = g_csr[i + j];
        uint2 u[16];
#pragma unroll
        for (int j = 0; j < 16; j++)
            u[j] = *reinterpret_cast<const uint2*>(tmp + (size_t)s[j] * 128 + lane * 4);
        float ns[16];
#pragma unroll
        for (int j = 0; j < 16; j++) ns[j] = __ldg(&g_nsrc[s[j]]);
#pragma unroll
        for (int j = 0; j < 16; j++) {
            float2 f = h2fu(u[j].x);
            acc.x += f.x * ns[j]; acc.y += f.y * ns[j];
            f = h2fu(u[j].y);
            acc.z += f.x * ns[j]; acc.w += f.y * ns[j];
        }
    }
    for (; i + 7 < end; i += 8) {
        int s[8];
#pragma unroll
        for (int j = 0; j < 8; j++) s[j] = g_csr[i + j];
        uint2 u[8];
#pragma unroll
        for (int j = 0; j < 8; j++)
            u[j] = *reinterpret_cast<const uint2*>(tmp + (size_t)s[j] * 128 + lane * 4);
#pragma unroll
        for (int j = 0; j < 8; j++) {
            float nsj = __ldg(&g_nsrc[s[j]]);
            float2 f = h2fu(u[j].x);
            acc.x += f.x * nsj; acc.y += f.y * nsj;
            f = h2fu(u[j].y);
            acc.z += f.x * nsj; acc.w += f.y * nsj;
        }
    }
    for (; i < end; i++) {
        int s = g_csr[i];
        uint2 u = *reinterpret_cast<const uint2*>(tmp + (size_t)s * 128 + lane * 4);
        float ns = __ldg(&g_nsrc[s]);
        float2 f;
        f = h2fu(u.x); acc.x += f.x * ns; acc.y += f.y * ns;
        f = h2fu(u.y); acc.z += f.x * ns; acc.w += f.y * ns;
    }
    float nd = g_ndst[w];
    float4 bb = *reinterpret_cast<const float4*>(b + lane * 4);
    __half2 p0 = __floats2half2_rn(acc.x * nd + bb.x, acc.y * nd + bb.y);
    __half2 p1 = __floats2half2_rn(acc.z * nd + bb.z, acc.w * nd + bb.w);
    uint2 st = make_uint2(*reinterpret_cast<unsigned*>(&p0),
                          *reinterpret_cast<unsigned*>(&p1));
    *reinterpret_cast<uint2*>(h + (size_t)w * 128 + lane * 4) = st;
}

// 64 features fp16 gather + n_src, fused finalize + softmax. warp per node, half2 per lane.
// 16-edge unroll.
__global__ void spmm_csr64h_softmax_k(const __half* __restrict__ tmp,
                                      const float* __restrict__ b,
                                      float* __restrict__ out) {
    int w = (blockIdx.x * blockDim.x + threadIdx.x) >> 5;
    int lane = threadIdx.x & 31;
    if (w >= N_NODES) return;
    int beg = g_rowptr[w];
    int end = g_rowptr[w + 1];
    float2 acc = make_float2(0.f, 0.f);
    int i = beg;
    for (; i + 15 < end; i += 16) {
        int s[16];
#pragma unroll
        for (int j = 0; j < 16; j++) s[j] = g_csr[i + j];
        unsigned v[16];
#pragma unroll
        for (int j = 0; j < 16; j++)
            v[j] = *reinterpret_cast<const unsigned*>(tmp + (size_t)s[j] * 64 + lane * 2);
        float ns[16];
#pragma unroll
        for (int j = 0; j < 16; j++) ns[j] = __ldg(&g_nsrc[s[j]]);
#pragma unroll
        for (int j = 0; j < 16; j++) {
            float2 f = h2fu(v[j]);
            acc.x += f.x * ns[j]; acc.y += f.y * ns[j];
        }
    }
    for (; i < end; i++) {
        int s = g_csr[i];
        float ns = __ldg(&g_nsrc[s]);
        float2 f = h2fu(*reinterpret_cast<const unsigned*>(tmp + (size_t)s * 64 + lane * 2));
        acc.x += f.x * ns; acc.y += f.y * ns;
    }
    float nd = g_ndst[w];
    float2 bb = *reinterpret_cast<const float2*>(b + lane * 2);
    float a0 = acc.x * nd + bb.x;
    float a1 = acc.y * nd + bb.y;
    float m = fmaxf(a0, a1);
#pragma unroll
    for (int o = 16; o > 0; o >>= 1) m = fmaxf(m, __shfl_xor_sync(0xffffffffu, m, o));
    float e0 = __expf(a0 - m);
    float e1 = __expf(a1 - m);
    float s = e0 + e1;
#pragma unroll
    for (int o = 16; o > 0; o >>= 1) s += __shfl_xor_sync(0xffffffffu, s, o);
    float inv = 1.f / s;
    reinterpret_cast<float2*>(out + (size_t)w * 64)[lane] = make_float2(e0 * inv, e1 * inv);
}

// ---------------- launch ----------------

extern "C" void kernel_launch(void* const* d_in, const int* in_sizes, int n_in,
                              void* d_out, int out_size) {
    const float* x = (const float*)d_in[0];
    const int* src = (const int*)d_in[1];
    const int* dst = (const int*)d_in[2];
    const float* W0 = (const float*)d_in[3];
    const float* b0 = (const float*)d_in[4];
    const float* W1 = (const float*)d_in[5];
    const float* b1 = (const float*)d_in[6];
    const float* W2 = (const float*)d_in[7];
    const float* b2 = (const float*)d_in[8];
    float* out = (float*)d_out;

    __half *xh, *tmph, *hh, *w0h, *w1h, *w2h;
    cudaGetSymbolAddress((void**)&xh, g_xh);
    cudaGetSymbolAddress((void**)&tmph, g_tmph);
    cudaGetSymbolAddress((void**)&hh, g_hh);
    cudaGetSymbolAddress((void**)&w0h, g_W0h);
    cudaGetSymbolAddress((void**)&w1h, g_W1h);
    cudaGetSymbolAddress((void**)&w2h, g_W2h);

    // one-time host objects (no device memory)
    static cudaStream_t s_side = nullptr;
    static cudaEvent_t s_fork = nullptr, s_join = nullptr;
    if (s_side == nullptr) {
        cudaStreamCreateWithFlags(&s_side, cudaStreamNonBlocking);
        cudaEventCreateWithFlags(&s_fork, cudaEventDisableTiming);
        cudaEventCreateWithFlags(&s_join, cudaEventDisableTiming);
    }

    const int TPB = 256;
    const int nodeBlocks = (N_NODES + TPB - 1) / TPB;
    const int edge2Blocks = (E_EDGES / 2 + TPB - 1) / TPB;
    const int edge4Blocks = (E_EDGES / 4 + TPB - 1) / TPB;
    const int nodeWarpBlocks = (int)(((size_t)N_NODES * 32 + TPB - 1) / TPB);
    const int gemmBlocks = N_PAD / 128;   // 782

    // fork: fp16 conversions + layer-0 GEMM on side stream (independent of CSR build)
    cudaEventRecord(s_fork, 0);
    cudaStreamWaitEvent(s_side, s_fork, 0);
    f2h4_k<<<2048, TPB, 0, s_side>>>((const float4*)x, (uint2*)xh, N_NODES * NFEAT / 4);
    f2h4_k<<<32, TPB, 0, s_side>>>((const float4*)W0, (uint2*)w0h, NFEAT * NHID / 4);
    f2h4_k<<<16, TPB, 0, s_side>>>((const float4*)W1, (uint2*)w1h, NHID * NHID / 4);
    f2h4_k<<<8, TPB, 0, s_side>>>((const float4*)W2, (uint2*)w2h, NHID * NCLASS / 4);
    gemm_wmma_k<NFEAT, NHID><<<gemmBlocks, 256, 0, s_side>>>(xh, w0h, tmph);
    cudaEventRecord(s_join, s_side);

    // CSR build chain on main stream (concurrent with conversions + GEMM0)
    zero_deg_k<<<nodeBlocks, TPB>>>();
    degree_k<<<edge2Blocks, TPB>>>((const int2*)src, (const int2*)dst);
    norms_k<<<nodeBlocks, TPB>>>();
    blocksum_k<<<SCAN_NB, 256>>>();
    scanblocks_k<<<1, 128>>>();
    localscan_k<<<SCAN_NB, 256>>>();
    scatter_k<<<edge4Blocks, TPB>>>((const int4*)src, (const int4*)dst);

    // join
    cudaStreamWaitEvent(0, s_join, 0);

    // ---- Layer 0 ----
    spmm_csr128h_k<<<nodeWarpBlocks, TPB>>>(tmph, b0, hh);

    // ---- Layer 1: 128 -> 128 ----
    gemm_wmma_k<NHID, NHID><<<gemmBlocks, 256>>>(hh, w1h, tmph);
    spmm_csr128h_k<<<nodeWarpBlocks, TPB>>>(tmph, b1, hh);

    // ---- Layer 2: 128 -> 64, + softmax ----
    gemm_wmma_k<NHID, NCLASS><<<gemmBlocks, 256>>>(hh, w2h, tmph);
    spmm_csr64h_softmax_k<<<nodeWarpBlocks, TPB>>>(tmph, b2, out);
}

// round 15
// speedup vs baseline: 1.8186x; 1.1624x over previous
#include <cuda_runtime.h>
#include <cuda_bf16.h>
#include <cuda_fp16.h>
#include <mma.h>
#include <math.h>

using namespace nvcuda;

#define N_NODES 100000
#define N_PAD 100096          // 782 * 128
#define E_EDGES 3200000
#define NFEAT 256
#define NHID 128
#define NCLASS 64

#define SCAN_CHUNK 1024
#define SCAN_NB ((N_NODES + SCAN_CHUNK - 1) / SCAN_CHUNK)   // 98

// Scratch (allocation-free rule: __device__ globals; zero-initialized)
__device__ __align__(256) __half g_xh[(size_t)N_PAD * NFEAT];     // x in fp16
__device__ __align__(256) __half g_tmph[(size_t)N_PAD * NHID];    // Z / hop ping
__device__ __align__(256) __half g_hh[(size_t)N_PAD * NHID];      // hop pong
__device__ __align__(256) float g_W01f[NFEAT * NHID];             // W0*W1 (fp32)
__device__ __align__(256) float g_W012f[NFEAT * NCLASS];          // W0*W1*W2 (fp32)
__device__ __align__(256) __half g_W012h[NFEAT * NCLASS];
__device__ __align__(256) float g_bt[NHID];                       // b0*W1
__device__ __align__(256) float g_c2[NCLASS];                     // b0*W1*W2
__device__ __align__(256) float g_c1[NCLASS];                     // b1*W2
__device__ __align__(256) float g_s1[N_NODES];                    // S*1
__device__ __align__(256) float g_s2[N_NODES];                    // S*S*1
__device__ __align__(256) float g_nsrc[N_NODES];
__device__ __align__(256) float g_ndst[N_NODES];
__device__ __align__(256) int g_degout[N_NODES];
__device__ __align__(256) int g_degin[N_NODES];
__device__ __align__(256) int g_rowptr[N_NODES + 1];
__device__ __align__(256) int g_cursor[N_NODES];
__device__ __align__(256) int g_csr[E_EDGES];
__device__ __align__(256) int g_blocksums[SCAN_NB];

__device__ __forceinline__ float2 h2fu(unsigned u) {
    return __half22float2(*reinterpret_cast<__half2*>(&u));
}

// ---------------- fp32 -> fp16 converter ----------------

__global__ void f2h4_k(const float4* __restrict__ src, uint2* __restrict__ dst, int n4) {
    int stride = gridDim.x * blockDim.x;
    for (int i = blockIdx.x * blockDim.x + threadIdx.x; i < n4; i += stride) {
        float4 v = src[i];
        __half2 h0 = __floats2half2_rn(v.x, v.y);
        __half2 h1 = __floats2half2_rn(v.z, v.w);
        dst[i] = make_uint2(*reinterpret_cast<unsigned*>(&h0),
                            *reinterpret_cast<unsigned*>(&h1));
    }
}

// ---------------- tiny fp32 GEMMs for weight/bias combination ----------------

// C[M x N] = A[M x K] * B[K x N], one thread per output element (K=128)
__global__ void matmul128_f32_k(const float* __restrict__ A,
                                const float* __restrict__ B,
                                float* __restrict__ C, int N, int total) {
    int idx = blockIdx.x * blockDim.x + threadIdx.x;
    if (idx >= total) return;
    int i = idx / N, j = idx % N;
    float acc = 0.f;
#pragma unroll 8
    for (int k = 0; k < 128; k++) acc += A[i * 128 + k] * B[k * N + j];
    C[idx] = acc;
}

// g_bt = b0 * W1   (128 threads)
__global__ void biascomb1_k(const float* __restrict__ b0, const float* __restrict__ W1) {
    int j = threadIdx.x;
    float acc = 0.f;
#pragma unroll 8
    for (int k = 0; k < 128; k++) acc += b0[k] * W1[k * 128 + j];
    g_bt[j] = acc;
}

// g_c2 = g_bt * W2 ; g_c1 = b1 * W2   (128 threads)
__global__ void biascomb2_k(const float* __restrict__ b1, const float* __restrict__ W2) {
    int j = threadIdx.x;
    if (j < 64) {
        float acc = 0.f;
#pragma unroll 8
        for (int k = 0; k < 128; k++) acc += g_bt[k] * W2[k * 64 + j];
        g_c2[j] = acc;
    } else {
        int c = j - 64;
        float acc = 0.f;
#pragma unroll 8
        for (int k = 0; k < 128; k++) acc += b1[k] * W2[k * 64 + c];
        g_c1[c] = acc;
    }
}

// ---------------- degree / norms ----------------

__global__ void zero_deg_k() {
    int i = blockIdx.x * blockDim.x + threadIdx.x;
    if (i < N_NODES) { g_degout[i] = 0; g_degin[i] = 0; }
}

__global__ void degree_k(const int2* __restrict__ src2,
                         const int2* __restrict__ dst2) {
    int e = blockIdx.x * blockDim.x + threadIdx.x;
    if (e < E_EDGES / 2) {
        int2 s = src2[e];
        int2 d = dst2[e];
        atomicAdd(&g_degout[s.x], 1);
        atomicAdd(&g_degout[s.y], 1);
        atomicAdd(&g_degin[d.x], 1);
        atomicAdd(&g_degin[d.y], 1);
    }
}

__global__ void norms_k() {
    int i = blockIdx.x * blockDim.x + threadIdx.x;
    if (i < N_NODES) {
        int dov = g_degout[i];
        int div_ = g_degin[i];
        g_nsrc[i] = rsqrtf((float)(dov > 0 ? dov : 1));
        g_ndst[i] = rsqrtf((float)(div_ > 0 ? div_ : 1));
    }
}

// ---------------- 3-phase exclusive scan of deg_in -> rowptr/cursor ----------------

__global__ void blocksum_k() {
    int base = blockIdx.x * SCAN_CHUNK;
    int tid = threadIdx.x;
    int s = 0;
#pragma unroll
    for (int j = 0; j < 4; j++) {
        int idx = base + tid * 4 + j;
        if (idx < N_NODES) s += g_degin[idx];
    }
#pragma unroll
    for (int o = 16; o > 0; o >>= 1) s += __shfl_xor_sync(0xffffffffu, s, o);
    __shared__ int ws[8];
    if ((tid & 31) == 0) ws[tid >> 5] = s;
    __syncthreads();
    if (tid == 0) {
        int t = 0;
#pragma unroll
        for (int w = 0; w < 8; w++) t += ws[w];
        g_blocksums[blockIdx.x] = t;
    }
}

__global__ void scanblocks_k() {
    __shared__ int s[128];
    int tid = threadIdx.x;
    int v = (tid < SCAN_NB) ? g_blocksums[tid] : 0;
    s[tid] = v;
    __syncthreads();
#pragma unroll
    for (int off = 1; off < 128; off <<= 1) {
        int t = (tid >= off) ? s[tid - off] : 0;
        __syncthreads();
        s[tid] += t;
        __syncthreads();
    }
    if (tid < SCAN_NB) g_blocksums[tid] = s[tid] - v;  // exclusive
}

__global__ void localscan_k() {
    int base = blockIdx.x * SCAN_CHUNK;
    int tid = threadIdx.x;
    int lane = tid & 31;
    int warp = tid >> 5;

    int e0 = base + tid * 4;
    int d0 = (e0 + 0 < N_NODES) ? g_degin[e0 + 0] : 0;
    int d1 = (e0 + 1 < N_NODES) ? g_degin[e0 + 1] : 0;
    int d2 = (e0 + 2 < N_NODES) ? g_degin[e0 + 2] : 0;
    int d3 = (e0 + 3 < N_NODES) ? g_degin[e0 + 3] : 0;
    int tsum = d0 + d1 + d2 + d3;

    int inc = tsum;
#pragma unroll
    for (int o = 1; o < 32; o <<= 1) {
        int t = __shfl_up_sync(0xffffffffu, inc, o);
        if (lane >= o) inc += t;
    }
    __shared__ int wsum[8];
    if (lane == 31) wsum[warp] = inc;
    __syncthreads();
    __shared__ int woff[8];
    if (tid == 0) {
        int acc = 0;
#pragma unroll
        for (int w = 0; w < 8; w++) { woff[w] = acc; acc += wsum[w]; }
    }
    __syncthreads();

    int thread_excl = g_blocksums[blockIdx.x] + woff[warp] + (inc - tsum);
    int p0 = thread_excl;
    int p1 = p0 + d0;
    int p2 = p1 + d1;
    int p3 = p2 + d2;
    if (e0 + 0 < N_NODES) { g_rowptr[e0 + 0] = p0; g_cursor[e0 + 0] = p0; }
    if (e0 + 1 < N_NODES) { g_rowptr[e0 + 1] = p1; g_cursor[e0 + 1] = p1; }
    if (e0 + 2 < N_NODES) { g_rowptr[e0 + 2] = p2; g_cursor[e0 + 2] = p2; }
    if (e0 + 3 < N_NODES) { g_rowptr[e0 + 3] = p3; g_cursor[e0 + 3] = p3; }
    if (blockIdx.x == 0 && tid == 0) g_rowptr[N_NODES] = E_EDGES;
}

__global__ void scatter_k(const int4* __restrict__ src4,
                          const int4* __restrict__ dst4) {
    int e = blockIdx.x * blockDim.x + threadIdx.x;
    if (e < E_EDGES / 4) {
        int4 s = src4[e];
        int4 d = dst4[e];
        g_csr[atomicAdd(&g_cursor[d.x], 1)] = s.x;
        g_csr[atomicAdd(&g_cursor[d.y], 1)] = s.y;
        g_csr[atomicAdd(&g_cursor[d.z], 1)] = s.z;
        g_csr[atomicAdd(&g_cursor[d.w], 1)] = s.w;
    }
}

// ---------------- scalar SpMV: s = ndst .* A (nsrc [.* s1]) ----------------

template <bool SECOND>
__global__ void spmv_k() {
    int w = (blockIdx.x * blockDim.x + threadIdx.x) >> 5;
    int lane = threadIdx.x & 31;
    if (w >= N_NODES) return;
    int beg = g_rowptr[w];
    int end = g_rowptr[w + 1];
    float acc = 0.f;
    for (int i = beg + lane; i < end; i += 32) {
        int s = g_csr[i];
        float v = g_nsrc[s];
        if (SECOND) v *= g_s1[s];
        acc += v;
    }
#pragma unroll
    for (int o = 16; o > 0; o >>= 1) acc += __shfl_xor_sync(0xffffffffu, acc, o);
    if (lane == 0) {
        float r = acc * g_ndst[w];
        if (SECOND) g_s2[w] = r; else g_s1[w] = r;
    }
}

// ---------------- WMMA GEMM: C = A * B  (half x half -> fp32 -> half) ----------------
template <int IN, int OUT>
__global__ void gemm_wmma_k(const __half* __restrict__ A,
                            const __half* __restrict__ B,
                            __half* __restrict__ C) {
    constexpr int FC = OUT / 32;
    __shared__ float stage[8][256];

    int wid = threadIdx.x >> 5;
    int lane = threadIdx.x & 31;
    int wr = wid >> 1;
    int wc = wid & 1;
    int row0 = blockIdx.x * 128 + wr * 32;
    int col0 = wc * (OUT / 2);

    wmma::fragment<wmma::accumulator, 16, 16, 16, float> acc[2][FC];
#pragma unroll
    for (int i = 0; i < 2; i++)
#pragma unroll
        for (int j = 0; j < FC; j++)
            wmma::fill_fragment(acc[i][j], 0.0f);

    for (int k = 0; k < IN; k += 16) {
        wmma::fragment<wmma::matrix_a, 16, 16, 16, __half, wmma::row_major> af0, af1;
        wmma::load_matrix_sync(af0, A + (size_t)row0 * IN + k, IN);
        wmma::load_matrix_sync(af1, A + (size_t)(row0 + 16) * IN + k, IN);
#pragma unroll
        for (int j = 0; j < FC; j++) {
            wmma::fragment<wmma::matrix_b, 16, 16, 16, __half, wmma::row_major> bf;
            wmma::load_matrix_sync(bf, B + (size_t)k * OUT + col0 + j * 16, OUT);
            wmma::mma_sync(acc[0][j], af0, bf, acc[0][j]);
            wmma::mma_sync(acc[1][j], af1, bf, acc[1][j]);
        }
    }

#pragma unroll
    for (int i = 0; i < 2; i++)
#pragma unroll
        for (int j = 0; j < FC; j++) {
            wmma::store_matrix_sync(stage[wid], acc[i][j], 16, wmma::mem_row_major);
            __syncwarp();
            const float* sp = stage[wid] + (lane >> 1) * 16 + (lane & 1) * 8;
            __half2 h0 = __floats2half2_rn(sp[0], sp[1]);
            __half2 h1 = __floats2half2_rn(sp[2], sp[3]);
            __half2 h2 = __floats2half2_rn(sp[4], sp[5]);
            __half2 h3 = __floats2half2_rn(sp[6], sp[7]);
            uint4 st = make_uint4(*reinterpret_cast<unsigned*>(&h0),
                                  *reinterpret_cast<unsigned*>(&h1),
                                  *reinterpret_cast<unsigned*>(&h2),
                                  *reinterpret_cast<unsigned*>(&h3));
            size_t off = (size_t)(row0 + i * 16 + (lane >> 1)) * OUT
                       + col0 + j * 16 + (lane & 1) * 8;
            *reinterpret_cast<uint4*>(C + off) = st;
            __syncwarp();
        }
}

// ---------------- hop: Y_out[d] = ndst[d] * sum_{s in N(d)} nsrc[s] * Y_in[s]  (64 cols) ----
// warp per dst node, half2 per lane, fp32 accumulate, fp16 out. 16-edge unroll.
__global__ void hop64_k(const __half* __restrict__ in, __half* __restrict__ outh) {
    int w = (blockIdx.x * blockDim.x + threadIdx.x) >> 5;
    int lane = threadIdx.x & 31;
    if (w >= N_NODES) return;
    int beg = g_rowptr[w];
    int end = g_rowptr[w + 1];
    float2 acc = make_float2(0.f, 0.f);
    int i = beg;
    for (; i + 15 < end; i += 16) {
        int s[16];
#pragma unroll
        for (int j = 0; j < 16; j++) s[j] = g_csr[i + j];
        unsigned v[16];
#pragma unroll
        for (int j = 0; j < 16; j++)
            v[j] = *reinterpret_cast<const unsigned*>(in + (size_t)s[j] * 64 + lane * 2);
        float ns[16];
#pragma unroll
        for (int j = 0; j < 16; j++) ns[j] = __ldg(&g_nsrc[s[j]]);
#pragma unroll
        for (int j = 0; j < 16; j++) {
            float2 f = h2fu(v[j]);
            acc.x += f.x * ns[j]; acc.y += f.y * ns[j];
        }
    }
    for (; i < end; i++) {
        int s = g_csr[i];
        float ns = __ldg(&g_nsrc[s]);
        float2 f = h2fu(*reinterpret_cast<const unsigned*>(in + (size_t)s * 64 + lane * 2));
        acc.x += f.x * ns; acc.y += f.y * ns;
    }
    float nd = g_ndst[w];
    __half2 p = __floats2half2_rn(acc.x * nd, acc.y * nd);
    *reinterpret_cast<unsigned*>(outh + (size_t)w * 64 + lane * 2) =
        *reinterpret_cast<unsigned*>(&p);
}

// ---------------- final hop + rank-1 bias corrections + softmax -> fp32 out ----------------
__global__ void final64_k(const __half* __restrict__ in,
                          const float* __restrict__ b2,
                          float* __restrict__ out) {
    int w = (blockIdx.x * blockDim.x + threadIdx.x) >> 5;
    int lane = threadIdx.x & 31;
    if (w >= N_NODES) return;
    int beg = g_rowptr[w];
    int end = g_rowptr[w + 1];
    float2 acc = make_float2(0.f, 0.f);
    int i = beg;
    for (; i + 15 < end; i += 16) {
        int s[16];
#pragma unroll
        for (int j = 0; j < 16; j++) s[j] = g_csr[i + j];
        unsigned v[16];
#pragma unroll
        for (int j = 0; j < 16; j++)
            v[j] = *reinterpret_cast<const unsigned*>(in + (size_t)s[j] * 64 + lane * 2);
        float ns[16];
#pragma unroll
        for (int j = 0; j < 16; j++) ns[j] = __ldg(&g_nsrc[s[j]]);
#pragma unroll
        for (int j = 0; j < 16; j++) {
            float2 f = h2fu(v[j]);
            acc.x += f.x * ns[j]; acc.y += f.y * ns[j];
        }
    }
    for (; i < end; i++) {
        int s = g_csr[i];
        float ns = __ldg(&g_nsrc[s]);
        float2 f = h2fu(*reinterpret_cast<const unsigned*>(in + (size_t)s * 64 + lane * 2));
        acc.x += f.x * ns; acc.y += f.y * ns;
    }
    float nd = g_ndst[w];
    float s1v = g_s1[w];
    float s2v = g_s2[w];
    float2 c1v = *reinterpret_cast<const float2*>(g_c1 + lane * 2);
    float2 c2v = *reinterpret_cast<const float2*>(g_c2 + lane * 2);
    float2 bb = *reinterpret_cast<const float2*>(b2 + lane * 2);
    float a0 = acc.x * nd + s2v * c2v.x + s1v * c1v.x + bb.x;
    float a1 = acc.y * nd + s2v * c2v.y + s1v * c1v.y + bb.y;
    float m = fmaxf(a0, a1);
#pragma unroll
    for (int o = 16; o > 0; o >>= 1) m = fmaxf(m, __shfl_xor_sync(0xffffffffu, m, o));
    float e0 = __expf(a0 - m);
    float e1 = __expf(a1 - m);
    float s = e0 + e1;
#pragma unroll
    for (int o = 16; o > 0; o >>= 1) s += __shfl_xor_sync(0xffffffffu, s, o);
    float inv = 1.f / s;
    reinterpret_cast<float2*>(out + (size_t)w * 64)[lane] = make_float2(e0 * inv, e1 * inv);
}

// ---------------- launch ----------------

extern "C" void kernel_launch(void* const* d_in, const int* in_sizes, int n_in,
                              void* d_out, int out_size) {
    const float* x = (const float*)d_in[0];
    const int* src = (const int*)d_in[1];
    const int* dst = (const int*)d_in[2];
    const float* W0 = (const float*)d_in[3];
    const float* b0 = (const float*)d_in[4];
    const float* W1 = (const float*)d_in[5];
    const float* b1 = (const float*)d_in[6];
    const float* W2 = (const float*)d_in[7];
    const float* b2 = (const float*)d_in[8];
    float* out = (float*)d_out;

    __half *xh, *tmph, *hh, *w012h;
    float *w01f, *w012f;
    cudaGetSymbolAddress((void**)&xh, g_xh);
    cudaGetSymbolAddress((void**)&tmph, g_tmph);
    cudaGetSymbolAddress((void**)&hh, g_hh);
    cudaGetSymbolAddress((void**)&w01f, g_W01f);
    cudaGetSymbolAddress((void**)&w012f, g_W012f);
    cudaGetSymbolAddress((void**)&w012h, g_W012h);

    // one-time host objects (no device memory)
    static cudaStream_t s_side = nullptr;
    static cudaEvent_t s_fork = nullptr, s_join = nullptr;
    if (s_side == nullptr) {
        cudaStreamCreateWithFlags(&s_side, cudaStreamNonBlocking);
        cudaEventCreateWithFlags(&s_fork, cudaEventDisableTiming);
        cudaEventCreateWithFlags(&s_join, cudaEventDisableTiming);
    }

    const int TPB = 256;
    const int nodeBlocks = (N_NODES + TPB - 1) / TPB;
    const int edge2Blocks = (E_EDGES / 2 + TPB - 1) / TPB;
    const int edge4Blocks = (E_EDGES / 4 + TPB - 1) / TPB;
    const int nodeWarpBlocks = (int)(((size_t)N_NODES * 32 + TPB - 1) / TPB);
    const int gemmBlocks = N_PAD / 128;   // 782

    // fork: side stream — X convert, weight/bias combine, Z = X * W012
    cudaEventRecord(s_fork, 0);
    cudaStreamWaitEvent(s_side, s_fork, 0);
    f2h4_k<<<2048, TPB, 0, s_side>>>((const float4*)x, (uint2*)xh, N_NODES * NFEAT / 4);
    matmul128_f32_k<<<(NFEAT * NHID) / TPB, TPB, 0, s_side>>>(W0, W1, w01f, NHID, NFEAT * NHID);
    matmul128_f32_k<<<(NFEAT * NCLASS) / TPB, TPB, 0, s_side>>>(w01f, W2, w012f, NCLASS, NFEAT * NCLASS);
    biascomb1_k<<<1, 128, 0, s_side>>>(b0, W1);
    biascomb2_k<<<1, 128, 0, s_side>>>(b1, W2);
    f2h4_k<<<16, TPB, 0, s_side>>>((const float4*)w012f, (uint2*)w012h, NFEAT * NCLASS / 4);
    gemm_wmma_k<NFEAT, NCLASS><<<gemmBlocks, 256, 0, s_side>>>(xh, w012h, tmph);
    cudaEventRecord(s_join, s_side);

    // main stream: CSR build + s1/s2 SpMVs (concurrent with side)
    zero_deg_k<<<nodeBlocks, TPB>>>();
    degree_k<<<edge2Blocks, TPB>>>((const int2*)src, (const int2*)dst);
    norms_k<<<nodeBlocks, TPB>>>();
    blocksum_k<<<SCAN_NB, 256>>>();
    scanblocks_k<<<1, 128>>>();
    localscan_k<<<SCAN_NB, 256>>>();
    scatter_k<<<edge4Blocks, TPB>>>((const int4*)src, (const int4*)dst);
    spmv_k<false><<<nodeWarpBlocks, TPB>>>();
    spmv_k<true><<<nodeWarpBlocks, TPB>>>();

    // join
    cudaStreamWaitEvent(0, s_join, 0);

    // three 64-wide hops of S; final fuses rank-1 bias terms + softmax
    hop64_k<<<nodeWarpBlocks, TPB>>>(tmph, hh);
    hop64_k<<<nodeWarpBlocks, TPB>>>(hh, tmph);
    final64_k<<<nodeWarpBlocks, TPB>>>(tmph, b2, out);
}

// round 16
// speedup vs baseline: 2.0740x; 1.1404x over previous
#include <cuda_runtime.h>
#include <cuda_bf16.h>
#include <cuda_fp16.h>
#include <mma.h>
#include <math.h>

using namespace nvcuda;

#define N_NODES 100000
#define N_PAD 100096          // 782 * 128
#define E_EDGES 3200000
#define NFEAT 256
#define NHID 128
#define NCLASS 64

#define SCAN_CHUNK 1024
#define SCAN_NB ((N_NODES + SCAN_CHUNK - 1) / SCAN_CHUNK)   // 98

// Scratch (allocation-free rule: __device__ globals; zero-initialized)
__device__ __align__(256) __half g_xh[(size_t)N_PAD * NFEAT];     // x in fp16
__device__ __align__(256) __half g_tmph[(size_t)N_PAD * NHID];    // Z / hop ping
__device__ __align__(256) __half g_hh[(size_t)N_PAD * NHID];      // hop pong
__device__ __align__(256) float g_W01f[NFEAT * NHID];             // W0*W1 (fp32)
__device__ __align__(256) float g_W012f[NFEAT * NCLASS];          // W0*W1*W2 (fp32)
__device__ __align__(256) __half g_W012h[NFEAT * NCLASS];
__device__ __align__(256) float g_bt[NHID];                       // b0*W1
__device__ __align__(256) float g_c2[NCLASS];                     // b0*W1*W2
__device__ __align__(256) float g_c1[NCLASS];                     // b1*W2
__device__ __align__(256) float g_s1[N_NODES];                    // S*1
__device__ __align__(256) float g_s2[N_NODES];                    // S*S*1
__device__ __align__(256) float g_nsrc[N_NODES];
__device__ __align__(256) float g_ndst[N_NODES];
__device__ __align__(256) float g_nd[N_NODES];                    // nsrc*ndst
__device__ __align__(256) int g_degout[N_NODES];
__device__ __align__(256) int g_degin[N_NODES];
__device__ __align__(256) int g_rowptr[N_NODES + 1];
__device__ __align__(256) int g_cursor[N_NODES];
__device__ __align__(256) int g_csr[E_EDGES];
__device__ __align__(256) int g_blocksums[SCAN_NB];

__device__ __forceinline__ float2 h2fu(unsigned u) {
    return __half22float2(*reinterpret_cast<__half2*>(&u));
}

// ---------------- fp32 -> fp16 converter ----------------

__global__ void f2h4_k(const float4* __restrict__ src, uint2* __restrict__ dst, int n4) {
    int stride = gridDim.x * blockDim.x;
    for (int i = blockIdx.x * blockDim.x + threadIdx.x; i < n4; i += stride) {
        float4 v = src[i];
        __half2 h0 = __floats2half2_rn(v.x, v.y);
        __half2 h1 = __floats2half2_rn(v.z, v.w);
        dst[i] = make_uint2(*reinterpret_cast<unsigned*>(&h0),
                            *reinterpret_cast<unsigned*>(&h1));
    }
}

// ---------------- tiny fp32 GEMMs for weight/bias combination ----------------

__global__ void matmul128_f32_k(const float* __restrict__ A,
                                const float* __restrict__ B,
                                float* __restrict__ C, int N, int total) {
    int idx = blockIdx.x * blockDim.x + threadIdx.x;
    if (idx >= total) return;
    int i = idx / N, j = idx % N;
    float acc = 0.f;
#pragma unroll 8
    for (int k = 0; k < 128; k++) acc += A[i * 128 + k] * B[k * N + j];
    C[idx] = acc;
}

__global__ void biascomb1_k(const float* __restrict__ b0, const float* __restrict__ W1) {
    int j = threadIdx.x;
    float acc = 0.f;
#pragma unroll 8
    for (int k = 0; k < 128; k++) acc += b0[k] * W1[k * 128 + j];
    g_bt[j] = acc;
}

__global__ void biascomb2_k(const float* __restrict__ b1, const float* __restrict__ W2) {
    int j = threadIdx.x;
    if (j < 64) {
        float acc = 0.f;
#pragma unroll 8
        for (int k = 0; k < 128; k++) acc += g_bt[k] * W2[k * 64 + j];
        g_c2[j] = acc;
    } else {
        int c = j - 64;
        float acc = 0.f;
#pragma unroll 8
        for (int k = 0; k < 128; k++) acc += b1[k] * W2[k * 64 + c];
        g_c1[c] = acc;
    }
}

// ---------------- degree / norms ----------------

__global__ void zero_deg_k() {
    int i = blockIdx.x * blockDim.x + threadIdx.x;
    if (i < N_NODES) { g_degout[i] = 0; g_degin[i] = 0; }
}

__global__ void degree_k(const int2* __restrict__ src2,
                         const int2* __restrict__ dst2) {
    int e = blockIdx.x * blockDim.x + threadIdx.x;
    if (e < E_EDGES / 2) {
        int2 s = src2[e];
        int2 d = dst2[e];
        atomicAdd(&g_degout[s.x], 1);
        atomicAdd(&g_degout[s.y], 1);
        atomicAdd(&g_degin[d.x], 1);
        atomicAdd(&g_degin[d.y], 1);
    }
}

__global__ void norms_k() {
    int i = blockIdx.x * blockDim.x + threadIdx.x;
    if (i < N_NODES) {
        int dov = g_degout[i];
        int div_ = g_degin[i];
        float ns = rsqrtf((float)(dov > 0 ? dov : 1));
        float nd = rsqrtf((float)(div_ > 0 ? div_ : 1));
        g_nsrc[i] = ns;
        g_ndst[i] = nd;
        g_nd[i] = ns * nd;
    }
}

// ---------------- 3-phase exclusive scan of deg_in -> rowptr/cursor ----------------

__global__ void blocksum_k() {
    int base = blockIdx.x * SCAN_CHUNK;
    int tid = threadIdx.x;
    int s = 0;
#pragma unroll
    for (int j = 0; j < 4; j++) {
        int idx = base + tid * 4 + j;
        if (idx < N_NODES) s += g_degin[idx];
    }
#pragma unroll
    for (int o = 16; o > 0; o >>= 1) s += __shfl_xor_sync(0xffffffffu, s, o);
    __shared__ int ws[8];
    if ((tid & 31) == 0) ws[tid >> 5] = s;
    __syncthreads();
    if (tid == 0) {
        int t = 0;
#pragma unroll
        for (int w = 0; w < 8; w++) t += ws[w];
        g_blocksums[blockIdx.x] = t;
    }
}

__global__ void scanblocks_k() {
    __shared__ int s[128];
    int tid = threadIdx.x;
    int v = (tid < SCAN_NB) ? g_blocksums[tid] : 0;
    s[tid] = v;
    __syncthreads();
#pragma unroll
    for (int off = 1; off < 128; off <<= 1) {
        int t = (tid >= off) ? s[tid - off] : 0;
        __syncthreads();
        s[tid] += t;
        __syncthreads();
    }
    if (tid < SCAN_NB) g_blocksums[tid] = s[tid] - v;  // exclusive
}

__global__ void localscan_k() {
    int base = blockIdx.x * SCAN_CHUNK;
    int tid = threadIdx.x;
    int lane = tid & 31;
    int warp = tid >> 5;

    int e0 = base + tid * 4;
    int d0 = (e0 + 0 < N_NODES) ? g_degin[e0 + 0] : 0;
    int d1 = (e0 + 1 < N_NODES) ? g_degin[e0 + 1] : 0;
    int d2 = (e0 + 2 < N_NODES) ? g_degin[e0 + 2] : 0;
    int d3 = (e0 + 3 < N_NODES) ? g_degin[e0 + 3] : 0;
    int tsum = d0 + d1 + d2 + d3;

    int inc = tsum;
#pragma unroll
    for (int o = 1; o < 32; o <<= 1) {
        int t = __shfl_up_sync(0xffffffffu, inc, o);
        if (lane >= o) inc += t;
    }
    __shared__ int wsum[8];
    if (lane == 31) wsum[warp] = inc;
    __syncthreads();
    __shared__ int woff[8];
    if (tid == 0) {
        int acc = 0;
#pragma unroll
        for (int w = 0; w < 8; w++) { woff[w] = acc; acc += wsum[w]; }
    }
    __syncthreads();

    int thread_excl = g_blocksums[blockIdx.x] + woff[warp] + (inc - tsum);
    int p0 = thread_excl;
    int p1 = p0 + d0;
    int p2 = p1 + d1;
    int p3 = p2 + d2;
    if (e0 + 0 < N_NODES) { g_rowptr[e0 + 0] = p0; g_cursor[e0 + 0] = p0; }
    if (e0 + 1 < N_NODES) { g_rowptr[e0 + 1] = p1; g_cursor[e0 + 1] = p1; }
    if (e0 + 2 < N_NODES) { g_rowptr[e0 + 2] = p2; g_cursor[e0 + 2] = p2; }
    if (e0 + 3 < N_NODES) { g_rowptr[e0 + 3] = p3; g_cursor[e0 + 3] = p3; }
    if (blockIdx.x == 0 && tid == 0) g_rowptr[N_NODES] = E_EDGES;
}

__global__ void scatter_k(const int4* __restrict__ src4,
                          const int4* __restrict__ dst4) {
    int e = blockIdx.x * blockDim.x + threadIdx.x;
    if (e < E_EDGES / 4) {
        int4 s = src4[e];
        int4 d = dst4[e];
        g_csr[atomicAdd(&g_cursor[d.x], 1)] = s.x;
        g_csr[atomicAdd(&g_cursor[d.y], 1)] = s.y;
        g_csr[atomicAdd(&g_cursor[d.z], 1)] = s.z;
        g_csr[atomicAdd(&g_cursor[d.w], 1)] = s.w;
    }
}

// ---------------- scalar SpMV: s = ndst .* A (nsrc [.* s1]) ----------------

template <bool SECOND>
__global__ void spmv_k() {
    int w = (blockIdx.x * blockDim.x + threadIdx.x) >> 5;
    int lane = threadIdx.x & 31;
    if (w >= N_NODES) return;
    int beg = g_rowptr[w];
    int end = g_rowptr[w + 1];
    float acc = 0.f;
    for (int i = beg + lane; i < end; i += 32) {
        int s = g_csr[i];
        float v = g_nsrc[s];
        if (SECOND) v *= g_s1[s];
        acc += v;
    }
#pragma unroll
    for (int o = 16; o > 0; o >>= 1) acc += __shfl_xor_sync(0xffffffffu, acc, o);
    if (lane == 0) {
        float r = acc * g_ndst[w];
        if (SECOND) g_s2[w] = r; else g_s1[w] = r;
    }
}

// ---------------- WMMA GEMM: C = D_s * (A * B)  (half x half -> fp32 -> half) ------------
// Epilogue scales each output row by g_nsrc[row] (pre-scaling for the hop chain).
template <int IN, int OUT>
__global__ void gemm_wmma_k(const __half* __restrict__ A,
                            const __half* __restrict__ B,
                            __half* __restrict__ C) {
    constexpr int FC = OUT / 32;
    __shared__ float stage[8][256];

    int wid = threadIdx.x >> 5;
    int lane = threadIdx.x & 31;
    int wr = wid >> 1;
    int wc = wid & 1;
    int row0 = blockIdx.x * 128 + wr * 32;
    int col0 = wc * (OUT / 2);

    wmma::fragment<wmma::accumulator, 16, 16, 16, float> acc[2][FC];
#pragma unroll
    for (int i = 0; i < 2; i++)
#pragma unroll
        for (int j = 0; j < FC; j++)
            wmma::fill_fragment(acc[i][j], 0.0f);

    for (int k = 0; k < IN; k += 16) {
        wmma::fragment<wmma::matrix_a, 16, 16, 16, __half, wmma::row_major> af0, af1;
        wmma::load_matrix_sync(af0, A + (size_t)row0 * IN + k, IN);
        wmma::load_matrix_sync(af1, A + (size_t)(row0 + 16) * IN + k, IN);
#pragma unroll
        for (int j = 0; j < FC; j++) {
            wmma::fragment<wmma::matrix_b, 16, 16, 16, __half, wmma::row_major> bf;
            wmma::load_matrix_sync(bf, B + (size_t)k * OUT + col0 + j * 16, OUT);
            wmma::mma_sync(acc[0][j], af0, bf, acc[0][j]);
            wmma::mma_sync(acc[1][j], af1, bf, acc[1][j]);
        }
    }

#pragma unroll
    for (int i = 0; i < 2; i++)
#pragma unroll
        for (int j = 0; j < FC; j++) {
            wmma::store_matrix_sync(stage[wid], acc[i][j], 16, wmma::mem_row_major);
            __syncwarp();
            int row = row0 + i * 16 + (lane >> 1);
            float ns = (row < N_NODES) ? g_nsrc[row] : 0.f;
            const float* sp = stage[wid] + (lane >> 1) * 16 + (lane & 1) * 8;
            __half2 h0 = __floats2half2_rn(sp[0] * ns, sp[1] * ns);
            __half2 h1 = __floats2half2_rn(sp[2] * ns, sp[3] * ns);
            __half2 h2 = __floats2half2_rn(sp[4] * ns, sp[5] * ns);
            __half2 h3 = __floats2half2_rn(sp[6] * ns, sp[7] * ns);
            uint4 st = make_uint4(*reinterpret_cast<unsigned*>(&h0),
                                  *reinterpret_cast<unsigned*>(&h1),
                                  *reinterpret_cast<unsigned*>(&h2),
                                  *reinterpret_cast<unsigned*>(&h3));
            size_t off = (size_t)row * OUT + col0 + j * 16 + (lane & 1) * 8;
            *reinterpret_cast<uint4*>(C + off) = st;
            __syncwarp();
        }
}

// ---------------- hop: pure neighbor sum, post-scale by nsrc*ndst (64 cols) ---------------
// warp per dst node, half2 per lane, fp32 accumulate, fp16 out. 16-edge unroll, NO per-edge
// scale loads (pre-scaled input).
__global__ void hop64_k(const __half* __restrict__ in, __half* __restrict__ outh) {
    int w = (blockIdx.x * blockDim.x + threadIdx.x) >> 5;
    int lane = threadIdx.x & 31;
    if (w >= N_NODES) return;
    int beg = g_rowptr[w];
    int end = g_rowptr[w + 1];
    float2 acc = make_float2(0.f, 0.f);
    int i = beg;
    for (; i + 15 < end; i += 16) {
        int s[16];
#pragma unroll
        for (int j = 0; j < 16; j++) s[j] = g_csr[i + j];
        unsigned v[16];
#pragma unroll
        for (int j = 0; j < 16; j++)
            v[j] = *reinterpret_cast<const unsigned*>(in + (size_t)s[j] * 64 + lane * 2);
#pragma unroll
        for (int j = 0; j < 16; j++) {
            float2 f = h2fu(v[j]);
            acc.x += f.x; acc.y += f.y;
        }
    }
    for (; i < end; i++) {
        int s = g_csr[i];
        float2 f = h2fu(*reinterpret_cast<const unsigned*>(in + (size_t)s * 64 + lane * 2));
        acc.x += f.x; acc.y += f.y;
    }
    float sc = g_nd[w];
    __half2 p = __floats2half2_rn(acc.x * sc, acc.y * sc);
    *reinterpret_cast<unsigned*>(outh + (size_t)w * 64 + lane * 2) =
        *reinterpret_cast<unsigned*>(&p);
}

// ---------------- final hop (pure sum) + ndst scale + rank-1 bias + softmax ---------------
__global__ void final64_k(const __half* __restrict__ in,
                          const float* __restrict__ b2,
                          float* __restrict__ out) {
    int w = (blockIdx.x * blockDim.x + threadIdx.x) >> 5;
    int lane = threadIdx.x & 31;
    if (w >= N_NODES) return;
    int beg = g_rowptr[w];
    int end = g_rowptr[w + 1];
    float2 acc = make_float2(0.f, 0.f);
    int i = beg;
    for (; i + 15 < end; i += 16) {
        int s[16];
#pragma unroll
        for (int j = 0; j < 16; j++) s[j] = g_csr[i + j];
        unsigned v[16];
#pragma unroll
        for (int j = 0; j < 16; j++)
            v[j] = *reinterpret_cast<const unsigned*>(in + (size_t)s[j] * 64 + lane * 2);
#pragma unroll
        for (int j = 0; j < 16; j++) {
            float2 f = h2fu(v[j]);
            acc.x += f.x; acc.y += f.y;
        }
    }
    for (; i < end; i++) {
        int s = g_csr[i];
        float2 f = h2fu(*reinterpret_cast<const unsigned*>(in + (size_t)s * 64 + lane * 2));
        acc.x += f.x; acc.y += f.y;
    }
    float nd = g_ndst[w];
    float s1v = g_s1[w];
    float s2v = g_s2[w];
    float2 c1v = *reinterpret_cast<const float2*>(g_c1 + lane * 2);
    float2 c2v = *reinterpret_cast<const float2*>(g_c2 + lane * 2);
    float2 bb = *reinterpret_cast<const float2*>(b2 + lane * 2);
    float a0 = acc.x * nd + s2v * c2v.x + s1v * c1v.x + bb.x;
    float a1 = acc.y * nd + s2v * c2v.y + s1v * c1v.y + bb.y;
    float m = fmaxf(a0, a1);
#pragma unroll
    for (int o = 16; o > 0; o >>= 1) m = fmaxf(m, __shfl_xor_sync(0xffffffffu, m, o));
    float e0 = __expf(a0 - m);
    float e1 = __expf(a1 - m);
    float s = e0 + e1;
#pragma unroll
    for (int o = 16; o > 0; o >>= 1) s += __shfl_xor_sync(0xffffffffu, s, o);
    float inv = 1.f / s;
    reinterpret_cast<float2*>(out + (size_t)w * 64)[lane] = make_float2(e0 * inv, e1 * inv);
}

// ---------------- launch ----------------

extern "C" void kernel_launch(void* const* d_in, const int* in_sizes, int n_in,
                              void* d_out, int out_size) {
    const float* x = (const float*)d_in[0];
    const int* src = (const int*)d_in[1];
    const int* dst = (const int*)d_in[2];
    const float* W0 = (const float*)d_in[3];
    const float* b0 = (const float*)d_in[4];
    const float* W1 = (const float*)d_in[5];
    const float* b1 = (const float*)d_in[6];
    const float* W2 = (const float*)d_in[7];
    const float* b2 = (const float*)d_in[8];
    float* out = (float*)d_out;

    __half *xh, *tmph, *hh, *w012h;
    float *w01f, *w012f;
    cudaGetSymbolAddress((void**)&xh, g_xh);
    cudaGetSymbolAddress((void**)&tmph, g_tmph);
    cudaGetSymbolAddress((void**)&hh, g_hh);
    cudaGetSymbolAddress((void**)&w01f, g_W01f);
    cudaGetSymbolAddress((void**)&w012f, g_W012f);
    cudaGetSymbolAddress((void**)&w012h, g_W012h);

    // one-time host objects (no device memory)
    static cudaStream_t s_side = nullptr;
    static cudaEvent_t s_fork = nullptr, s_join = nullptr;
    if (s_side == nullptr) {
        cudaStreamCreateWithFlags(&s_side, cudaStreamNonBlocking);
        cudaEventCreateWithFlags(&s_fork, cudaEventDisableTiming);
        cudaEventCreateWithFlags(&s_join, cudaEventDisableTiming);
    }

    const int TPB = 256;
    const int nodeBlocks = (N_NODES + TPB - 1) / TPB;
    const int edge2Blocks = (E_EDGES / 2 + TPB - 1) / TPB;
    const int edge4Blocks = (E_EDGES / 4 + TPB - 1) / TPB;
    const int nodeWarpBlocks = (int)(((size_t)N_NODES * 32 + TPB - 1) / TPB);
    const int gemmBlocks = N_PAD / 128;   // 782

    // main stream FIRST: norms are needed by the side-stream GEMM epilogue, so the
    // fork point is after norms_k. Degrees/norms are cheap (~25 us); overlap the rest.
    zero_deg_k<<<nodeBlocks, TPB>>>();
    degree_k<<<edge2Blocks, TPB>>>((const int2*)src, (const int2*)dst);
    norms_k<<<nodeBlocks, TPB>>>();

    // fork: side stream — X convert, weight/bias combine, Z_hat = D_s * (X * W012)
    cudaEventRecord(s_fork, 0);
    cudaStreamWaitEvent(s_side, s_fork, 0);
    f2h4_k<<<2048, TPB, 0, s_side>>>((const float4*)x, (uint2*)xh, N_NODES * NFEAT / 4);
    matmul128_f32_k<<<(NFEAT * NHID) / TPB, TPB, 0, s_side>>>(W0, W1, w01f, NHID, NFEAT * NHID);
    matmul128_f32_k<<<(NFEAT * NCLASS) / TPB, TPB, 0, s_side>>>(w01f, W2, w012f, NCLASS, NFEAT * NCLASS);
    biascomb1_k<<<1, 128, 0, s_side>>>(b0, W1);
    biascomb2_k<<<1, 128, 0, s_side>>>(b1, W2);
    f2h4_k<<<16, TPB, 0, s_side>>>((const float4*)w012f, (uint2*)w012h, NFEAT * NCLASS / 4);
    gemm_wmma_k<NFEAT, NCLASS><<<gemmBlocks, 256, 0, s_side>>>(xh, w012h, tmph);
    cudaEventRecord(s_join, s_side);

    // main stream: scan + scatter + s1/s2 SpMVs (concurrent with side)
    blocksum_k<<<SCAN_NB, 256>>>();
    scanblocks_k<<<1, 128>>>();
    localscan_k<<<SCAN_NB, 256>>>();
    scatter_k<<<edge4Blocks, TPB>>>((const int4*)src, (const int4*)dst);
    spmv_k<false><<<nodeWarpBlocks, TPB>>>();
    spmv_k<true><<<nodeWarpBlocks, TPB>>>();

    // join
    cudaStreamWaitEvent(0, s_join, 0);

    // three 64-wide hops (pure sums; scaling folded into epilogues)
    hop64_k<<<nodeWarpBlocks, TPB>>>(tmph, hh);
    hop64_k<<<nodeWarpBlocks, TPB>>>(hh, tmph);
    final64_k<<<nodeWarpBlocks, TPB>>>(tmph, b2, out);
}